// round 7
// baseline (speedup 1.0000x reference)
#include <cuda_runtime.h>
#include <cuda_bf16.h>
#include <math.h>
#include <stdint.h>

#define D_MODEL 1024
#define NHEAD   16
#define DK      64
#define BATCH   4
#define SEQ     2048
#define M_ROWS  (BATCH*SEQ)   // 8192
#define HQKV    (BATCH*NHEAD*SEQ*DK)

// Inter-kernel interchange: bf16 hi/lo pairs (value = hi+lo, err ~2^-18 rel)
__device__ __align__(16) __nv_bfloat16 g_xhi[M_ROWS*D_MODEL];
__device__ __align__(16) __nv_bfloat16 g_xlo[M_ROWS*D_MODEL];
__device__ __align__(16) __nv_bfloat16 g_Whi[4*D_MODEL*D_MODEL];   // q,k,v,o
__device__ __align__(16) __nv_bfloat16 g_Wlo[4*D_MODEL*D_MODEL];
__device__ __align__(16) __nv_bfloat16 g_Qhi[HQKV];  // [B,H,T,dk], pre-scaled 0.125
__device__ __align__(16) __nv_bfloat16 g_Qlo[HQKV];
__device__ __align__(16) __nv_bfloat16 g_Khi[HQKV];
__device__ __align__(16) __nv_bfloat16 g_Klo[HQKV];
__device__ __align__(16) __nv_bfloat16 g_Vhi[HQKV];
__device__ __align__(16) __nv_bfloat16 g_Vlo[HQKV];
__device__ __align__(16) __nv_bfloat16 g_ctxhi[M_ROWS*D_MODEL];
__device__ __align__(16) __nv_bfloat16 g_ctxlo[M_ROWS*D_MODEL];

// ---------------------------------------------------------------------------
__device__ __forceinline__ void ldmx4(uint32_t* r, uint32_t addr) {
    asm volatile("ldmatrix.sync.aligned.m8n8.x4.shared.b16 {%0,%1,%2,%3}, [%4];"
                 : "=r"(r[0]), "=r"(r[1]), "=r"(r[2]), "=r"(r[3]) : "r"(addr));
}
__device__ __forceinline__ void ldmx4t(uint32_t* r, uint32_t addr) {
    asm volatile("ldmatrix.sync.aligned.m8n8.x4.trans.shared.b16 {%0,%1,%2,%3}, [%4];"
                 : "=r"(r[0]), "=r"(r[1]), "=r"(r[2]), "=r"(r[3]) : "r"(addr));
}
__device__ __forceinline__ void mma_bf16(float* d, const uint32_t* a,
                                         uint32_t b0, uint32_t b1) {
    asm volatile(
        "mma.sync.aligned.m16n8k16.row.col.f32.bf16.bf16.f32 "
        "{%0,%1,%2,%3}, {%4,%5,%6,%7}, {%8,%9}, {%0,%1,%2,%3};"
        : "+f"(d[0]), "+f"(d[1]), "+f"(d[2]), "+f"(d[3])
        : "r"(a[0]), "r"(a[1]), "r"(a[2]), "r"(a[3]), "r"(b0), "r"(b1));
}
__device__ __forceinline__ uint32_t smem_u32(const void* p) {
    uint32_t a;
    asm("{ .reg .u64 t; cvta.to.shared.u64 t, %1; cvt.u32.u64 %0, t; }"
        : "=r"(a) : "l"(p));
    return a;
}
__device__ __forceinline__ uint32_t sw128(uint32_t off) {
    return off ^ ((off >> 3) & 0x70);
}
__device__ __forceinline__ unsigned short bf16bits(float f) {
    __nv_bfloat16 h = __float2bfloat16_rn(f);
    return *reinterpret_cast<unsigned short*>(&h);
}
__device__ __forceinline__ void split4(float4 v, uint2& H, uint2& L) {
    __nv_bfloat16 hx = __float2bfloat16_rn(v.x);
    __nv_bfloat16 hy = __float2bfloat16_rn(v.y);
    __nv_bfloat16 hz = __float2bfloat16_rn(v.z);
    __nv_bfloat16 hw = __float2bfloat16_rn(v.w);
    __nv_bfloat162 h0 = __halves2bfloat162(hx, hy);
    __nv_bfloat162 h1 = __halves2bfloat162(hz, hw);
    __nv_bfloat16 lx = __float2bfloat16_rn(v.x - __bfloat162float(hx));
    __nv_bfloat16 ly = __float2bfloat16_rn(v.y - __bfloat162float(hy));
    __nv_bfloat16 lz = __float2bfloat16_rn(v.z - __bfloat162float(hz));
    __nv_bfloat16 lw = __float2bfloat16_rn(v.w - __bfloat162float(hw));
    __nv_bfloat162 l0 = __halves2bfloat162(lx, ly);
    __nv_bfloat162 l1 = __halves2bfloat162(lz, lw);
    H.x = *reinterpret_cast<uint32_t*>(&h0);
    H.y = *reinterpret_cast<uint32_t*>(&h1);
    L.x = *reinterpret_cast<uint32_t*>(&l0);
    L.y = *reinterpret_cast<uint32_t*>(&l1);
}
__device__ __forceinline__ void split_pack2(float a, float b, uint32_t& H, uint32_t& L) {
    unsigned short ha = bf16bits(a), hb = bf16bits(b);
    float fa, fb;
    { __nv_bfloat16 t = *reinterpret_cast<__nv_bfloat16*>(&ha); fa = __bfloat162float(t); }
    { __nv_bfloat16 t = *reinterpret_cast<__nv_bfloat16*>(&hb); fb = __bfloat162float(t); }
    unsigned short la = bf16bits(a - fa), lb = bf16bits(b - fb);
    H = (uint32_t)ha | ((uint32_t)hb << 16);
    L = (uint32_t)la | ((uint32_t)lb << 16);
}

// ---------------------------------------------------------------------------
// Pre-split kernels (memory-bound, one-shot)
// ---------------------------------------------------------------------------
__global__ __launch_bounds__(256) void split_x_kernel(const float* __restrict__ x) {
    const int i = blockIdx.x * 256 + threadIdx.x;       // float4 index
    float4 v = ((const float4*)x)[i];
    v.x += 1e-8f; v.y += 1e-8f; v.z += 1e-8f; v.w += 1e-8f;
    uint2 H, L;
    split4(v, H, L);
    ((uint2*)g_xhi)[i] = H;
    ((uint2*)g_xlo)[i] = L;
}

__global__ __launch_bounds__(256) void split_w_kernel(const float* __restrict__ W0,
                                                      const float* __restrict__ W1,
                                                      const float* __restrict__ W2,
                                                      const float* __restrict__ W3) {
    const int which = blockIdx.y;
    const float* W = which == 0 ? W0 : which == 1 ? W1 : which == 2 ? W2 : W3;
    const int i = blockIdx.x * 256 + threadIdx.x;       // float4 index
    float4 v = ((const float4*)W)[i];
    uint2 H, L;
    split4(v, H, L);
    const size_t o = (size_t)which * (D_MODEL*D_MODEL/4) + i;
    ((uint2*)g_Whi)[o] = H;
    ((uint2*)g_Wlo)[o] = L;
}

// ---------------------------------------------------------------------------
// HMMA GEMM, bf16 hi/lo inputs (no in-loop conversion).
// CTA tile M=128, N=64, Kchunk=64; 8 warps 4(M)x2(N), warp tile 32x32.
// QKV=true : A = g_x{hi,lo}, W row = g_W{hi,lo}[which]; epilogue clip +-10,
//            split-write Q/K/V bf16 head layout (Q pre-scaled by 0.125).
// QKV=false: A = g_ctx{hi,lo}, W = g_W[3]; fp32 out, bias+clip +-100.
// ---------------------------------------------------------------------------
template<bool QKV>
__global__ __launch_bounds__(256)
void hmma_gemm_kernel(const float* __restrict__ b0v,
                      const float* __restrict__ b1v,
                      const float* __restrict__ b2v,
                      float* __restrict__ outp)
{
    __shared__ __align__(1024) unsigned char sAhi[128*128];
    __shared__ __align__(1024) unsigned char sAlo[128*128];
    __shared__ __align__(1024) unsigned char sBhi[64*128];
    __shared__ __align__(1024) unsigned char sBlo[64*128];

    const int tid  = threadIdx.x;
    const int wid  = tid >> 5;
    const int lane = tid & 31;
    const int mw   = wid & 3;
    const int nw   = wid >> 2;

    const int bx    = blockIdx.x;
    const int which = QKV ? (bx >> 4) : 3;
    const int n0    = (bx & 15) * 64;
    const int m0    = blockIdx.y * 128;

    const __nv_bfloat16* Ahi = QKV ? g_xhi : g_ctxhi;
    const __nv_bfloat16* Alo = QKV ? g_xlo : g_ctxlo;
    const __nv_bfloat16* Whi = g_Whi + (size_t)which * D_MODEL * D_MODEL;
    const __nv_bfloat16* Wlo = g_Wlo + (size_t)which * D_MODEL * D_MODEL;
    const float* bias = QKV ? (which == 0 ? b0v : which == 1 ? b1v : b2v) : b0v;

    const uint32_t baseAhi = smem_u32(sAhi);
    const uint32_t baseAlo = smem_u32(sAlo);
    const uint32_t baseBhi = smem_u32(sBhi);
    const uint32_t baseBlo = smem_u32(sBlo);

    const int blk      = lane >> 3;
    const int rr       = lane & 7;
    const int aRowHalf = blk & 1;
    const int aKHalf   = blk >> 1;
    const int bNb      = blk >> 1;
    const int bKHalf   = blk & 1;

    float acc[2][4][4];
    #pragma unroll
    for (int i=0;i<2;i++)
        #pragma unroll
        for (int j=0;j<4;j++)
            #pragma unroll
            for (int l=0;l<4;l++) acc[i][j][l]=0.f;

    for (int chunk = 0; chunk < 16; chunk++) {
        const int k0 = chunk * 64;

        // A tile: 128 rows x 64 bf16 (128B rows) = 8 uint4/row
        uint4 vah[4], val[4], vbh[2], vbl[2];
        #pragma unroll
        for (int i = 0; i < 4; i++) {
            const int f   = tid + i * 256;        // 0..1023
            const int row = f >> 3;
            const int c   = f & 7;
            const size_t go = (size_t)(m0 + row) * D_MODEL + k0 + c * 8;
            vah[i] = *(const uint4*)(Ahi + go);
            val[i] = *(const uint4*)(Alo + go);
        }
        #pragma unroll
        for (int i = 0; i < 2; i++) {
            const int f   = tid + i * 256;        // 0..511
            const int row = f >> 3;
            const int c   = f & 7;
            const size_t go = (size_t)(n0 + row) * D_MODEL + k0 + c * 8;
            vbh[i] = *(const uint4*)(Whi + go);
            vbl[i] = *(const uint4*)(Wlo + go);
        }

        __syncthreads();

        #pragma unroll
        for (int i = 0; i < 4; i++) {
            const int f   = tid + i * 256;
            const uint32_t sw = sw128((uint32_t)((f >> 3) * 128 + (f & 7) * 16));
            *(uint4*)(sAhi + sw) = vah[i];
            *(uint4*)(sAlo + sw) = val[i];
        }
        #pragma unroll
        for (int i = 0; i < 2; i++) {
            const int f   = tid + i * 256;
            const uint32_t sw = sw128((uint32_t)((f >> 3) * 128 + (f & 7) * 16));
            *(uint4*)(sBhi + sw) = vbh[i];
            *(uint4*)(sBlo + sw) = vbl[i];
        }
        __syncthreads();

        #pragma unroll
        for (int ks = 0; ks < 4; ks++) {
            uint32_t ah[2][4], al[2][4];
            #pragma unroll
            for (int mf = 0; mf < 2; mf++) {
                const uint32_t row = (uint32_t)(mw*32 + mf*16 + aRowHalf*8 + rr);
                const uint32_t off = sw128(row * 128 + (uint32_t)(ks*16 + aKHalf*8) * 2);
                ldmx4(ah[mf], baseAhi + off);
                ldmx4(al[mf], baseAlo + off);
            }
            uint32_t bh[2][4], bl[2][4];
            #pragma unroll
            for (int pr = 0; pr < 2; pr++) {
                const uint32_t n   = (uint32_t)(nw*32 + pr*16 + bNb*8 + rr);
                const uint32_t off = sw128(n * 128 + (uint32_t)(ks*16 + bKHalf*8) * 2);
                ldmx4(bh[pr], baseBhi + off);
                ldmx4(bl[pr], baseBlo + off);
            }
            #pragma unroll
            for (int mf = 0; mf < 2; mf++) {
                #pragma unroll
                for (int nb = 0; nb < 4; nb++) {
                    const uint32_t B0h = bh[nb>>1][(nb&1)*2+0];
                    const uint32_t B1h = bh[nb>>1][(nb&1)*2+1];
                    const uint32_t B0l = bl[nb>>1][(nb&1)*2+0];
                    const uint32_t B1l = bl[nb>>1][(nb&1)*2+1];
                    mma_bf16(acc[mf][nb], ah[mf], B0h, B1h);
                    mma_bf16(acc[mf][nb], ah[mf], B0l, B1l);
                    mma_bf16(acc[mf][nb], al[mf], B0h, B1h);
                }
            }
        }
    }

    const int gID = lane >> 2;
    const int tg  = lane & 3;

    #pragma unroll
    for (int mf = 0; mf < 2; mf++) {
        #pragma unroll
        for (int nb = 0; nb < 4; nb++) {
            const int colL = nw*32 + nb*8 + tg*2;
            const float bb0 = bias[n0 + colL];
            const float bb1 = bias[n0 + colL + 1];
            #pragma unroll
            for (int half = 0; half < 2; half++) {
                const int m = m0 + mw*32 + mf*16 + half*8 + gID;
                if (QKV && which < 3) {
                    float v0 = fminf(fmaxf(acc[mf][nb][half*2+0] + bb0, -10.f), 10.f);
                    float v1 = fminf(fmaxf(acc[mf][nb][half*2+1] + bb1, -10.f), 10.f);
                    if (which == 0) { v0 *= 0.125f; v1 *= 0.125f; }  // fold score scale
                    uint32_t H, L;
                    split_pack2(v0, v1, H, L);
                    const int b_ = m >> 11;
                    const int t  = m & (SEQ - 1);
                    const int h  = bx & 15;
                    const size_t o = (((size_t)(b_*NHEAD + h))*SEQ + t)*DK + colL;
                    __nv_bfloat16* dh = (which == 0) ? g_Qhi : (which == 1) ? g_Khi : g_Vhi;
                    __nv_bfloat16* dl = (which == 0) ? g_Qlo : (which == 1) ? g_Klo : g_Vlo;
                    *(uint32_t*)(dh + o) = H;
                    *(uint32_t*)(dl + o) = L;
                } else {
                    float2 v;
                    v.x = fminf(fmaxf(acc[mf][nb][half*2+0] + bb0, -100.f), 100.f);
                    v.y = fminf(fmaxf(acc[mf][nb][half*2+1] + bb1, -100.f), 100.f);
                    *(float2*)(outp + (size_t)m * D_MODEL + n0 + colL) = v;
                }
            }
        }
    }
}

// ---------------------------------------------------------------------------
// HMMA flash attention, bf16 hi/lo inputs. Max-free softmax (scores clipped
// to [-50,50]; p=exp(s) in range; mask -> p=0). V via trans-ldmatrix.
// Tile fills are pure 16B swizzled copies. ctx written as bf16 hi/lo.
// smem: phase0 [0,16K)=Qhi [16K,32K)=Qlo;
//       per tile [0,8K)=Khi [8K,16K)=Klo [16K,24K)=Vhi [24K,32K)=Vlo.
// ---------------------------------------------------------------------------
__global__ __launch_bounds__(256, 1)
void attn_hmma_kernel(const unsigned char* __restrict__ mask)
{
    __shared__ __align__(1024) unsigned char sbuf[32768];
    __shared__ unsigned char smask[64];

    const int tid  = threadIdx.x;
    const int wid  = tid >> 5;
    const int lane = tid & 31;
    const int gID  = lane >> 2;
    const int tg   = lane & 3;

    const int blk      = lane >> 3;
    const int rr       = lane & 7;
    const int aRowHalf = blk & 1;
    const int aKHalf   = blk >> 1;
    const int bNb      = blk >> 1;
    const int bKHalf   = blk & 1;

    const int vKey = lane & 15;
    const int vDh  = lane >> 4;

    const int qt = blockIdx.x;
    const int h  = blockIdx.y;
    const int b  = blockIdx.z;
    const int m0 = qt * 128;

    const size_t headoff = ((size_t)(b*NHEAD + h))*SEQ*DK;
    const __nv_bfloat16* Qhi = g_Qhi + headoff;
    const __nv_bfloat16* Qlo = g_Qlo + headoff;
    const __nv_bfloat16* Khi = g_Khi + headoff;
    const __nv_bfloat16* Klo = g_Klo + headoff;
    const __nv_bfloat16* Vhi = g_Vhi + headoff;
    const __nv_bfloat16* Vlo = g_Vlo + headoff;
    const unsigned char* mb = mask + (size_t)b*SEQ;

    const uint32_t sb = smem_u32(sbuf);

    // ---- Phase 0: Q tile 128x64 bf16 (pre-scaled) -> smem -> registers
    #pragma unroll
    for (int i = 0; i < 4; i++) {
        const int f   = tid + i * 256;       // 0..1023
        const int row = f >> 3;
        const int c   = f & 7;
        const size_t go = (size_t)(m0 + row) * DK + c * 8;
        const uint32_t sw = sw128((uint32_t)(row * 128 + c * 16));
        *(uint4*)(sbuf + sw)         = *(const uint4*)(Qhi + go);
        *(uint4*)(sbuf + 16384 + sw) = *(const uint4*)(Qlo + go);
    }
    __syncthreads();

    uint32_t qh[4][4], ql[4][4];
    #pragma unroll
    for (int ks = 0; ks < 4; ks++) {
        const uint32_t row = (uint32_t)(wid*16 + aRowHalf*8 + rr);
        const uint32_t off = sw128(row * 128 + (uint32_t)(ks*16 + aKHalf*8) * 2);
        ldmx4(qh[ks], sb + off);
        ldmx4(ql[ks], sb + 16384 + off);
    }
    __syncthreads();

    float oacc[8][4];
    #pragma unroll
    for (int nb = 0; nb < 8; nb++)
        #pragma unroll
        for (int i = 0; i < 4; i++) oacc[nb][i] = 0.f;
    float lrun0 = 0.f, lrun1 = 0.f;

    for (int kt = 0; kt < SEQ; kt += 64) {
        // ---- K/V tiles: 64 rows x 128B, pure swizzled copies
        #pragma unroll
        for (int i = 0; i < 2; i++) {
            const int f   = tid + i * 256;   // 0..511
            const int row = f >> 3;
            const int c   = f & 7;
            const size_t go = (size_t)(kt + row) * DK + c * 8;
            const uint32_t sw = sw128((uint32_t)(row * 128 + c * 16));
            *(uint4*)(sbuf + sw)         = *(const uint4*)(Khi + go);
            *(uint4*)(sbuf + 8192 + sw)  = *(const uint4*)(Klo + go);
            *(uint4*)(sbuf + 16384 + sw) = *(const uint4*)(Vhi + go);
            *(uint4*)(sbuf + 24576 + sw) = *(const uint4*)(Vlo + go);
        }
        if (tid < 16) ((uint32_t*)smask)[tid] = *(const uint32_t*)(mb + kt + tid*4);
        __syncthreads();

        // ---- QK^T
        float sacc[8][4];
        #pragma unroll
        for (int nt = 0; nt < 8; nt++)
            #pragma unroll
            for (int i = 0; i < 4; i++) sacc[nt][i] = 0.f;

        #pragma unroll
        for (int kg = 0; kg < 4; kg++) {
            #pragma unroll
            for (int ks = 0; ks < 4; ks++) {
                uint32_t bh[4], bl[4];
                const uint32_t row = (uint32_t)(kg*16 + bNb*8 + rr);
                const uint32_t off = sw128(row * 128 + (uint32_t)(ks*16 + bKHalf*8) * 2);
                ldmx4(bh, sb + off);
                ldmx4(bl, sb + 8192 + off);
                #pragma unroll
                for (int sub = 0; sub < 2; sub++) {
                    const int nt = kg*2 + sub;
                    mma_bf16(sacc[nt], qh[ks], bh[sub*2], bh[sub*2+1]);
                    mma_bf16(sacc[nt], qh[ks], bl[sub*2], bl[sub*2+1]);
                    mma_bf16(sacc[nt], ql[ks], bh[sub*2], bh[sub*2+1]);
                }
            }
        }

        // ---- clip, mask, p=exp(s), pack PV A-fragments, row sums
        uint32_t pah[4][4], pal[4][4];
        float rs0 = 0.f, rs1 = 0.f;
        #pragma unroll
        for (int nt = 0; nt < 8; nt++) {
            const int keyc = nt*8 + tg*2;
            const bool f0 = smask[keyc] != 0;
            const bool f1 = smask[keyc + 1] != 0;
            float s0 = fminf(fmaxf(sacc[nt][0], -50.f), 50.f); if (f0) s0 = -10000.f;
            float s1 = fminf(fmaxf(sacc[nt][1], -50.f), 50.f); if (f1) s1 = -10000.f;
            float s2 = fminf(fmaxf(sacc[nt][2], -50.f), 50.f); if (f0) s2 = -10000.f;
            float s3 = fminf(fmaxf(sacc[nt][3], -50.f), 50.f); if (f1) s3 = -10000.f;
            const float p0 = __expf(s0);
            const float p1 = __expf(s1);
            const float p2 = __expf(s2);
            const float p3 = __expf(s3);
            rs0 += p0 + p1;
            rs1 += p2 + p3;
            const int ks  = nt >> 1;
            const int sub = nt & 1;
            split_pack2(p0, p1, pah[ks][sub*2+0], pal[ks][sub*2+0]);
            split_pack2(p2, p3, pah[ks][sub*2+1], pal[ks][sub*2+1]);
        }
        rs0 += __shfl_xor_sync(0xffffffffu, rs0, 1);
        rs0 += __shfl_xor_sync(0xffffffffu, rs0, 2);
        rs1 += __shfl_xor_sync(0xffffffffu, rs1, 1);
        rs1 += __shfl_xor_sync(0xffffffffu, rs1, 2);
        lrun0 += rs0;
        lrun1 += rs1;

        // ---- PV (B via trans-ldmatrix)
        #pragma unroll
        for (int dg = 0; dg < 4; dg++) {
            #pragma unroll
            for (int ks = 0; ks < 4; ks++) {
                uint32_t vh[4], vl[4];
                const uint32_t key = (uint32_t)(ks*16 + vKey);
                const uint32_t off = sw128(key * 128 + (uint32_t)(dg*16 + vDh*8) * 2);
                ldmx4t(vh, sb + 16384 + off);
                ldmx4t(vl, sb + 24576 + off);
                #pragma unroll
                for (int sub = 0; sub < 2; sub++) {
                    const int nb = dg*2 + sub;
                    mma_bf16(oacc[nb], pah[ks], vh[sub*2], vh[sub*2+1]);
                    mma_bf16(oacc[nb], pah[ks], vl[sub*2], vl[sub*2+1]);
                    mma_bf16(oacc[nb], pal[ks], vh[sub*2], vh[sub*2+1]);
                }
            }
        }
        __syncthreads();
    }

    // ---- normalize, split, store ctx as bf16 hi/lo
    const float inv0 = 1.f / lrun0;
    const float inv1 = 1.f / lrun1;
    const int row0 = m0 + wid*16 + gID;
    const int row1 = row0 + 8;
    const size_t o0 = ((size_t)(b*SEQ + row0))*D_MODEL + h*DK;
    const size_t o1 = ((size_t)(b*SEQ + row1))*D_MODEL + h*DK;
    #pragma unroll
    for (int nb = 0; nb < 8; nb++) {
        const int col = nb*8 + tg*2;
        uint32_t H, L;
        split_pack2(oacc[nb][0]*inv0, oacc[nb][1]*inv0, H, L);
        *(uint32_t*)(g_ctxhi + o0 + col) = H;
        *(uint32_t*)(g_ctxlo + o0 + col) = L;
        split_pack2(oacc[nb][2]*inv1, oacc[nb][3]*inv1, H, L);
        *(uint32_t*)(g_ctxhi + o1 + col) = H;
        *(uint32_t*)(g_ctxlo + o1 + col) = L;
    }
}

// ---------------------------------------------------------------------------
extern "C" void kernel_launch(void* const* d_in, const int* in_sizes, int n_in,
                              void* d_out, int out_size)
{
    const float* x  = (const float*)d_in[0];
    const unsigned char* mask = (const unsigned char*)d_in[1];
    const float* Wq = (const float*)d_in[2];
    const float* bq = (const float*)d_in[3];
    const float* Wk = (const float*)d_in[4];
    const float* bk = (const float*)d_in[5];
    const float* Wv = (const float*)d_in[6];
    const float* bv = (const float*)d_in[7];
    const float* Wo = (const float*)d_in[8];
    const float* bo = (const float*)d_in[9];
    float* out = (float*)d_out;

    // Pre-split inputs into bf16 hi/lo interchange buffers
    split_x_kernel<<<M_ROWS*D_MODEL/4/256, 256>>>(x);
    split_w_kernel<<<dim3(D_MODEL*D_MODEL/4/256, 4), 256>>>(Wq, Wk, Wv, Wo);

    // Fused Q/K/V projections (grid.x: [0,16)=Q, [16,32)=K, [32,48)=V)
    hmma_gemm_kernel<true><<<dim3(48, M_ROWS/128), 256>>>(bq, bk, bv, nullptr);

    attn_hmma_kernel<<<dim3(SEQ/128, NHEAD, BATCH), 256>>>(mask);

    // Output projection (A = g_ctx hi/lo)
    hmma_gemm_kernel<false><<<dim3(16, M_ROWS/128), 256>>>(bo, bo, bo, out);
}

// round 8
// speedup vs baseline: 1.1632x; 1.1632x over previous
#include <cuda_runtime.h>
#include <cuda_bf16.h>
#include <math.h>
#include <stdint.h>

#define D_MODEL 1024
#define NHEAD   16
#define DK      64
#define BATCH   4
#define SEQ     2048
#define M_ROWS  (BATCH*SEQ)   // 8192
#define HQKV    (BATCH*NHEAD*SEQ*DK)

// Inter-kernel interchange: bf16 hi/lo pairs (value = hi+lo, err ~2^-18 rel)
__device__ __align__(16) __nv_bfloat16 g_xhi[M_ROWS*D_MODEL];
__device__ __align__(16) __nv_bfloat16 g_xlo[M_ROWS*D_MODEL];
__device__ __align__(16) __nv_bfloat16 g_Whi[4*D_MODEL*D_MODEL];   // q,k,v,o
__device__ __align__(16) __nv_bfloat16 g_Wlo[4*D_MODEL*D_MODEL];
__device__ __align__(16) __nv_bfloat16 g_Qhi[HQKV];  // [B,H,T,dk], pre-scaled 0.125
__device__ __align__(16) __nv_bfloat16 g_Qlo[HQKV];
__device__ __align__(16) __nv_bfloat16 g_Khi[HQKV];
__device__ __align__(16) __nv_bfloat16 g_Klo[HQKV];
__device__ __align__(16) __nv_bfloat16 g_Vhi[HQKV];
__device__ __align__(16) __nv_bfloat16 g_Vlo[HQKV];
__device__ __align__(16) __nv_bfloat16 g_ctxhi[M_ROWS*D_MODEL];
__device__ __align__(16) __nv_bfloat16 g_ctxlo[M_ROWS*D_MODEL];

// ---------------------------------------------------------------------------
__device__ __forceinline__ void ldmx4(uint32_t* r, uint32_t addr) {
    asm volatile("ldmatrix.sync.aligned.m8n8.x4.shared.b16 {%0,%1,%2,%3}, [%4];"
                 : "=r"(r[0]), "=r"(r[1]), "=r"(r[2]), "=r"(r[3]) : "r"(addr));
}
__device__ __forceinline__ void ldmx4t(uint32_t* r, uint32_t addr) {
    asm volatile("ldmatrix.sync.aligned.m8n8.x4.trans.shared.b16 {%0,%1,%2,%3}, [%4];"
                 : "=r"(r[0]), "=r"(r[1]), "=r"(r[2]), "=r"(r[3]) : "r"(addr));
}
__device__ __forceinline__ void mma_bf16(float* d, const uint32_t* a,
                                         uint32_t b0, uint32_t b1) {
    asm volatile(
        "mma.sync.aligned.m16n8k16.row.col.f32.bf16.bf16.f32 "
        "{%0,%1,%2,%3}, {%4,%5,%6,%7}, {%8,%9}, {%0,%1,%2,%3};"
        : "+f"(d[0]), "+f"(d[1]), "+f"(d[2]), "+f"(d[3])
        : "r"(a[0]), "r"(a[1]), "r"(a[2]), "r"(a[3]), "r"(b0), "r"(b1));
}
__device__ __forceinline__ uint32_t smem_u32(const void* p) {
    uint32_t a;
    asm("{ .reg .u64 t; cvta.to.shared.u64 t, %1; cvt.u32.u64 %0, t; }"
        : "=r"(a) : "l"(p));
    return a;
}
__device__ __forceinline__ void cp16(uint32_t saddr, const void* g) {
    asm volatile("cp.async.cg.shared.global [%0], [%1], 16;"
                 :: "r"(saddr), "l"(g) : "memory");
}
#define CP_COMMIT()   asm volatile("cp.async.commit_group;" ::: "memory")
#define CP_WAIT(n)    asm volatile("cp.async.wait_group %0;" :: "n"(n) : "memory")

__device__ __forceinline__ uint32_t sw128(uint32_t off) {
    return off ^ ((off >> 3) & 0x70);
}
__device__ __forceinline__ unsigned short bf16bits(float f) {
    __nv_bfloat16 h = __float2bfloat16_rn(f);
    return *reinterpret_cast<unsigned short*>(&h);
}
__device__ __forceinline__ void split4(float4 v, uint2& H, uint2& L) {
    __nv_bfloat16 hx = __float2bfloat16_rn(v.x);
    __nv_bfloat16 hy = __float2bfloat16_rn(v.y);
    __nv_bfloat16 hz = __float2bfloat16_rn(v.z);
    __nv_bfloat16 hw = __float2bfloat16_rn(v.w);
    __nv_bfloat162 h0 = __halves2bfloat162(hx, hy);
    __nv_bfloat162 h1 = __halves2bfloat162(hz, hw);
    __nv_bfloat16 lx = __float2bfloat16_rn(v.x - __bfloat162float(hx));
    __nv_bfloat16 ly = __float2bfloat16_rn(v.y - __bfloat162float(hy));
    __nv_bfloat16 lz = __float2bfloat16_rn(v.z - __bfloat162float(hz));
    __nv_bfloat16 lw = __float2bfloat16_rn(v.w - __bfloat162float(hw));
    __nv_bfloat162 l0 = __halves2bfloat162(lx, ly);
    __nv_bfloat162 l1 = __halves2bfloat162(lz, lw);
    H.x = *reinterpret_cast<uint32_t*>(&h0);
    H.y = *reinterpret_cast<uint32_t*>(&h1);
    L.x = *reinterpret_cast<uint32_t*>(&l0);
    L.y = *reinterpret_cast<uint32_t*>(&l1);
}
__device__ __forceinline__ void split_pack2(float a, float b, uint32_t& H, uint32_t& L) {
    unsigned short ha = bf16bits(a), hb = bf16bits(b);
    float fa, fb;
    { __nv_bfloat16 t = *reinterpret_cast<__nv_bfloat16*>(&ha); fa = __bfloat162float(t); }
    { __nv_bfloat16 t = *reinterpret_cast<__nv_bfloat16*>(&hb); fb = __bfloat162float(t); }
    unsigned short la = bf16bits(a - fa), lb = bf16bits(b - fb);
    H = (uint32_t)ha | ((uint32_t)hb << 16);
    L = (uint32_t)la | ((uint32_t)lb << 16);
}

// ---------------------------------------------------------------------------
// Pre-split kernels (memory-bound, one-shot)
// ---------------------------------------------------------------------------
__global__ __launch_bounds__(256) void split_x_kernel(const float* __restrict__ x) {
    const int i = blockIdx.x * 256 + threadIdx.x;
    float4 v = ((const float4*)x)[i];
    v.x += 1e-8f; v.y += 1e-8f; v.z += 1e-8f; v.w += 1e-8f;
    uint2 H, L;
    split4(v, H, L);
    ((uint2*)g_xhi)[i] = H;
    ((uint2*)g_xlo)[i] = L;
}

__global__ __launch_bounds__(256) void split_w_kernel(const float* __restrict__ W0,
                                                      const float* __restrict__ W1,
                                                      const float* __restrict__ W2,
                                                      const float* __restrict__ W3) {
    const int which = blockIdx.y;
    const float* W = which == 0 ? W0 : which == 1 ? W1 : which == 2 ? W2 : W3;
    const int i = blockIdx.x * 256 + threadIdx.x;
    float4 v = ((const float4*)W)[i];
    uint2 H, L;
    split4(v, H, L);
    const size_t o = (size_t)which * (D_MODEL*D_MODEL/4) + i;
    ((uint2*)g_Whi)[o] = H;
    ((uint2*)g_Wlo)[o] = L;
}

// ---------------------------------------------------------------------------
// HMMA GEMM, bf16 hi/lo inputs — unchanged from R7.
// ---------------------------------------------------------------------------
template<bool QKV>
__global__ __launch_bounds__(256)
void hmma_gemm_kernel(const float* __restrict__ b0v,
                      const float* __restrict__ b1v,
                      const float* __restrict__ b2v,
                      float* __restrict__ outp)
{
    __shared__ __align__(1024) unsigned char sAhi[128*128];
    __shared__ __align__(1024) unsigned char sAlo[128*128];
    __shared__ __align__(1024) unsigned char sBhi[64*128];
    __shared__ __align__(1024) unsigned char sBlo[64*128];

    const int tid  = threadIdx.x;
    const int wid  = tid >> 5;
    const int lane = tid & 31;
    const int mw   = wid & 3;
    const int nw   = wid >> 2;

    const int bx    = blockIdx.x;
    const int which = QKV ? (bx >> 4) : 3;
    const int n0    = (bx & 15) * 64;
    const int m0    = blockIdx.y * 128;

    const __nv_bfloat16* Ahi = QKV ? g_xhi : g_ctxhi;
    const __nv_bfloat16* Alo = QKV ? g_xlo : g_ctxlo;
    const __nv_bfloat16* Whi = g_Whi + (size_t)which * D_MODEL * D_MODEL;
    const __nv_bfloat16* Wlo = g_Wlo + (size_t)which * D_MODEL * D_MODEL;
    const float* bias = QKV ? (which == 0 ? b0v : which == 1 ? b1v : b2v) : b0v;

    const uint32_t baseAhi = smem_u32(sAhi);
    const uint32_t baseAlo = smem_u32(sAlo);
    const uint32_t baseBhi = smem_u32(sBhi);
    const uint32_t baseBlo = smem_u32(sBlo);

    const int blk      = lane >> 3;
    const int rr       = lane & 7;
    const int aRowHalf = blk & 1;
    const int aKHalf   = blk >> 1;
    const int bNb      = blk >> 1;
    const int bKHalf   = blk & 1;

    float acc[2][4][4];
    #pragma unroll
    for (int i=0;i<2;i++)
        #pragma unroll
        for (int j=0;j<4;j++)
            #pragma unroll
            for (int l=0;l<4;l++) acc[i][j][l]=0.f;

    for (int chunk = 0; chunk < 16; chunk++) {
        const int k0 = chunk * 64;

        uint4 vah[4], val[4], vbh[2], vbl[2];
        #pragma unroll
        for (int i = 0; i < 4; i++) {
            const int f   = tid + i * 256;
            const int row = f >> 3;
            const int c   = f & 7;
            const size_t go = (size_t)(m0 + row) * D_MODEL + k0 + c * 8;
            vah[i] = *(const uint4*)(Ahi + go);
            val[i] = *(const uint4*)(Alo + go);
        }
        #pragma unroll
        for (int i = 0; i < 2; i++) {
            const int f   = tid + i * 256;
            const int row = f >> 3;
            const int c   = f & 7;
            const size_t go = (size_t)(n0 + row) * D_MODEL + k0 + c * 8;
            vbh[i] = *(const uint4*)(Whi + go);
            vbl[i] = *(const uint4*)(Wlo + go);
        }

        __syncthreads();

        #pragma unroll
        for (int i = 0; i < 4; i++) {
            const int f   = tid + i * 256;
            const uint32_t sw = sw128((uint32_t)((f >> 3) * 128 + (f & 7) * 16));
            *(uint4*)(sAhi + sw) = vah[i];
            *(uint4*)(sAlo + sw) = val[i];
        }
        #pragma unroll
        for (int i = 0; i < 2; i++) {
            const int f   = tid + i * 256;
            const uint32_t sw = sw128((uint32_t)((f >> 3) * 128 + (f & 7) * 16));
            *(uint4*)(sBhi + sw) = vbh[i];
            *(uint4*)(sBlo + sw) = vbl[i];
        }
        __syncthreads();

        #pragma unroll
        for (int ks = 0; ks < 4; ks++) {
            uint32_t ah[2][4], al[2][4];
            #pragma unroll
            for (int mf = 0; mf < 2; mf++) {
                const uint32_t row = (uint32_t)(mw*32 + mf*16 + aRowHalf*8 + rr);
                const uint32_t off = sw128(row * 128 + (uint32_t)(ks*16 + aKHalf*8) * 2);
                ldmx4(ah[mf], baseAhi + off);
                ldmx4(al[mf], baseAlo + off);
            }
            uint32_t bh[2][4], bl[2][4];
            #pragma unroll
            for (int pr = 0; pr < 2; pr++) {
                const uint32_t n   = (uint32_t)(nw*32 + pr*16 + bNb*8 + rr);
                const uint32_t off = sw128(n * 128 + (uint32_t)(ks*16 + bKHalf*8) * 2);
                ldmx4(bh[pr], baseBhi + off);
                ldmx4(bl[pr], baseBlo + off);
            }
            #pragma unroll
            for (int mf = 0; mf < 2; mf++) {
                #pragma unroll
                for (int nb = 0; nb < 4; nb++) {
                    const uint32_t B0h = bh[nb>>1][(nb&1)*2+0];
                    const uint32_t B1h = bh[nb>>1][(nb&1)*2+1];
                    const uint32_t B0l = bl[nb>>1][(nb&1)*2+0];
                    const uint32_t B1l = bl[nb>>1][(nb&1)*2+1];
                    mma_bf16(acc[mf][nb], ah[mf], B0h, B1h);
                    mma_bf16(acc[mf][nb], ah[mf], B0l, B1l);
                    mma_bf16(acc[mf][nb], al[mf], B0h, B1h);
                }
            }
        }
    }

    const int gID = lane >> 2;
    const int tg  = lane & 3;

    #pragma unroll
    for (int mf = 0; mf < 2; mf++) {
        #pragma unroll
        for (int nb = 0; nb < 4; nb++) {
            const int colL = nw*32 + nb*8 + tg*2;
            const float bb0 = bias[n0 + colL];
            const float bb1 = bias[n0 + colL + 1];
            #pragma unroll
            for (int half = 0; half < 2; half++) {
                const int m = m0 + mw*32 + mf*16 + half*8 + gID;
                if (QKV && which < 3) {
                    float v0 = fminf(fmaxf(acc[mf][nb][half*2+0] + bb0, -10.f), 10.f);
                    float v1 = fminf(fmaxf(acc[mf][nb][half*2+1] + bb1, -10.f), 10.f);
                    if (which == 0) { v0 *= 0.125f; v1 *= 0.125f; }
                    uint32_t H, L;
                    split_pack2(v0, v1, H, L);
                    const int b_ = m >> 11;
                    const int t  = m & (SEQ - 1);
                    const int h  = bx & 15;
                    const size_t o = (((size_t)(b_*NHEAD + h))*SEQ + t)*DK + colL;
                    __nv_bfloat16* dh = (which == 0) ? g_Qhi : (which == 1) ? g_Khi : g_Vhi;
                    __nv_bfloat16* dl = (which == 0) ? g_Qlo : (which == 1) ? g_Klo : g_Vlo;
                    *(uint32_t*)(dh + o) = H;
                    *(uint32_t*)(dl + o) = L;
                } else {
                    float2 v;
                    v.x = fminf(fmaxf(acc[mf][nb][half*2+0] + bb0, -100.f), 100.f);
                    v.y = fminf(fmaxf(acc[mf][nb][half*2+1] + bb1, -100.f), 100.f);
                    *(float2*)(outp + (size_t)m * D_MODEL + n0 + colL) = v;
                }
            }
        }
    }
}

// ---------------------------------------------------------------------------
// HMMA flash attention v3: cp.async double-buffered K/V + interleaved MMA
// chains (accumulation dim outermost so consecutive MMAs hit different accs).
// Dynamic smem 64KB: buf[2] x {Khi@0,Klo@8K,Vhi@16K,Vlo@24K} (32KB each).
// Q phase borrows buf0 (Qhi@0, Qlo@16K).
// ---------------------------------------------------------------------------
#define ATTN_SMEM 65536
#define NT (SEQ/64)

__global__ __launch_bounds__(256, 1)
void attn_hmma_kernel(const unsigned char* __restrict__ mask)
{
    extern __shared__ __align__(1024) unsigned char sbuf[];
    __shared__ unsigned char smask[64];

    const int tid  = threadIdx.x;
    const int wid  = tid >> 5;
    const int lane = tid & 31;
    const int gID  = lane >> 2;
    const int tg   = lane & 3;

    const int blk      = lane >> 3;
    const int rr       = lane & 7;
    const int aRowHalf = blk & 1;
    const int aKHalf   = blk >> 1;
    const int bNb      = blk >> 1;
    const int bKHalf   = blk & 1;

    const int vKey = lane & 15;
    const int vDh  = lane >> 4;

    const int qt = blockIdx.x;
    const int h  = blockIdx.y;
    const int b  = blockIdx.z;
    const int m0 = qt * 128;

    const size_t headoff = ((size_t)(b*NHEAD + h))*SEQ*DK;
    const __nv_bfloat16* Qhi = g_Qhi + headoff;
    const __nv_bfloat16* Qlo = g_Qlo + headoff;
    const __nv_bfloat16* Khi = g_Khi + headoff;
    const __nv_bfloat16* Klo = g_Klo + headoff;
    const __nv_bfloat16* Vhi = g_Vhi + headoff;
    const __nv_bfloat16* Vlo = g_Vlo + headoff;
    const unsigned char* mb = mask + (size_t)b*SEQ;

    const uint32_t sb = smem_u32(sbuf);

    // Per-thread tile-fill addressing: 2 rows x 1 col of 16B per iteration pair
    const int frow0 = tid >> 3;            // 0..31
    const int fcol  = tid & 7;             // 0..7
    const uint32_t swf0 = sw128((uint32_t)(frow0 * 128 + fcol * 16));
    const uint32_t swf1 = sw128((uint32_t)((frow0 + 32) * 128 + fcol * 16));

    // ---- Phase 0: Q tile 128x64 bf16 (pre-scaled) -> smem -> registers
    #pragma unroll
    for (int i = 0; i < 4; i++) {
        const int f   = tid + i * 256;
        const int row = f >> 3;
        const int c   = f & 7;
        const size_t go = (size_t)(m0 + row) * DK + c * 8;
        const uint32_t sw = sw128((uint32_t)(row * 128 + c * 16));
        *(uint4*)(sbuf + sw)         = *(const uint4*)(Qhi + go);
        *(uint4*)(sbuf + 16384 + sw) = *(const uint4*)(Qlo + go);
    }
    __syncthreads();

    uint32_t qh[4][4], ql[4][4];
    #pragma unroll
    for (int ks = 0; ks < 4; ks++) {
        const uint32_t row = (uint32_t)(wid*16 + aRowHalf*8 + rr);
        const uint32_t off = sw128(row * 128 + (uint32_t)(ks*16 + aKHalf*8) * 2);
        ldmx4(qh[ks], sb + off);
        ldmx4(ql[ks], sb + 16384 + off);
    }
    __syncthreads();   // Q smem dead

    float oacc[8][4];
    #pragma unroll
    for (int nb = 0; nb < 8; nb++)
        #pragma unroll
        for (int i = 0; i < 4; i++) oacc[nb][i] = 0.f;
    float lrun0 = 0.f, lrun1 = 0.f;

    // ---- prologue: async-load tile 0 into buffer 0
    {
        const size_t g0 = (size_t)frow0 * DK + fcol * 8;
        const size_t g1 = (size_t)(frow0 + 32) * DK + fcol * 8;
        cp16(sb + swf0,         Khi + g0);  cp16(sb + swf1,         Khi + g1);
        cp16(sb +  8192 + swf0, Klo + g0);  cp16(sb +  8192 + swf1, Klo + g1);
        cp16(sb + 16384 + swf0, Vhi + g0);  cp16(sb + 16384 + swf1, Vhi + g1);
        cp16(sb + 24576 + swf0, Vlo + g0);  cp16(sb + 24576 + swf1, Vlo + g1);
        CP_COMMIT();
    }

    for (int t = 0; t < NT; t++) {
        const int kt = t * 64;
        const uint32_t cbuf = (uint32_t)(t & 1) * 32768;

        if (tid < 16) ((uint32_t*)smask)[tid] = *(const uint32_t*)(mb + kt + tid*4);

        if (t + 1 < NT) {
            const uint32_t nbuf = (uint32_t)((t + 1) & 1) * 32768;
            const size_t base = (size_t)(kt + 64) * DK;
            const size_t g0 = base + (size_t)frow0 * DK + fcol * 8;
            const size_t g1 = base + (size_t)(frow0 + 32) * DK + fcol * 8;
            cp16(sb + nbuf + swf0,         Khi + g0);  cp16(sb + nbuf + swf1,         Khi + g1);
            cp16(sb + nbuf +  8192 + swf0, Klo + g0);  cp16(sb + nbuf +  8192 + swf1, Klo + g1);
            cp16(sb + nbuf + 16384 + swf0, Vhi + g0);  cp16(sb + nbuf + 16384 + swf1, Vhi + g1);
            cp16(sb + nbuf + 24576 + swf0, Vlo + g0);  cp16(sb + nbuf + 24576 + swf1, Vlo + g1);
            CP_COMMIT();
            CP_WAIT(1);          // tile t's group complete; t+1 in flight
        } else {
            CP_WAIT(0);
        }
        __syncthreads();

        // ---- QK^T: ks (accumulation) outer, kg inner -> independent chains
        float sacc[8][4];
        #pragma unroll
        for (int nt = 0; nt < 8; nt++)
            #pragma unroll
            for (int i = 0; i < 4; i++) sacc[nt][i] = 0.f;

        #pragma unroll
        for (int ks = 0; ks < 4; ks++) {
            #pragma unroll
            for (int kg = 0; kg < 4; kg++) {
                uint32_t bh[4], bl[4];
                const uint32_t row = (uint32_t)(kg*16 + bNb*8 + rr);
                const uint32_t off = sw128(row * 128 + (uint32_t)(ks*16 + bKHalf*8) * 2);
                ldmx4(bh, sb + cbuf + off);
                ldmx4(bl, sb + cbuf + 8192 + off);
                #pragma unroll
                for (int sub = 0; sub < 2; sub++) {
                    const int nt = kg*2 + sub;
                    mma_bf16(sacc[nt], qh[ks], bh[sub*2], bh[sub*2+1]);
                    mma_bf16(sacc[nt], qh[ks], bl[sub*2], bl[sub*2+1]);
                    mma_bf16(sacc[nt], ql[ks], bh[sub*2], bh[sub*2+1]);
                }
            }
        }

        // ---- clip, mask, p=exp(s), pack PV A-fragments, row sums
        uint32_t pah[4][4], pal[4][4];
        float rs0 = 0.f, rs1 = 0.f;
        #pragma unroll
        for (int nt = 0; nt < 8; nt++) {
            const int keyc = nt*8 + tg*2;
            const bool f0 = smask[keyc] != 0;
            const bool f1 = smask[keyc + 1] != 0;
            float s0 = fminf(fmaxf(sacc[nt][0], -50.f), 50.f); if (f0) s0 = -10000.f;
            float s1 = fminf(fmaxf(sacc[nt][1], -50.f), 50.f); if (f1) s1 = -10000.f;
            float s2 = fminf(fmaxf(sacc[nt][2], -50.f), 50.f); if (f0) s2 = -10000.f;
            float s3 = fminf(fmaxf(sacc[nt][3], -50.f), 50.f); if (f1) s3 = -10000.f;
            const float p0 = __expf(s0);
            const float p1 = __expf(s1);
            const float p2 = __expf(s2);
            const float p3 = __expf(s3);
            rs0 += p0 + p1;
            rs1 += p2 + p3;
            const int ks  = nt >> 1;
            const int sub = nt & 1;
            split_pack2(p0, p1, pah[ks][sub*2+0], pal[ks][sub*2+0]);
            split_pack2(p2, p3, pah[ks][sub*2+1], pal[ks][sub*2+1]);
        }
        rs0 += __shfl_xor_sync(0xffffffffu, rs0, 1);
        rs0 += __shfl_xor_sync(0xffffffffu, rs0, 2);
        rs1 += __shfl_xor_sync(0xffffffffu, rs1, 1);
        rs1 += __shfl_xor_sync(0xffffffffu, rs1, 2);
        lrun0 += rs0;
        lrun1 += rs1;

        // ---- PV: ks (accumulation over keys) outer, dg inner
        #pragma unroll
        for (int ks = 0; ks < 4; ks++) {
            #pragma unroll
            for (int dg = 0; dg < 4; dg++) {
                uint32_t vh[4], vl[4];
                const uint32_t key = (uint32_t)(ks*16 + vKey);
                const uint32_t off = sw128(key * 128 + (uint32_t)(dg*16 + vDh*8) * 2);
                ldmx4t(vh, sb + cbuf + 16384 + off);
                ldmx4t(vl, sb + cbuf + 24576 + off);
                #pragma unroll
                for (int sub = 0; sub < 2; sub++) {
                    const int nb = dg*2 + sub;
                    mma_bf16(oacc[nb], pah[ks], vh[sub*2], vh[sub*2+1]);
                    mma_bf16(oacc[nb], pah[ks], vl[sub*2], vl[sub*2+1]);
                    mma_bf16(oacc[nb], pal[ks], vh[sub*2], vh[sub*2+1]);
                }
            }
        }
        __syncthreads();   // all warps done with buf[t&1] before t+2 overwrites
    }

    // ---- normalize, split, store ctx as bf16 hi/lo
    const float inv0 = 1.f / lrun0;
    const float inv1 = 1.f / lrun1;
    const int row0 = m0 + wid*16 + gID;
    const int row1 = row0 + 8;
    const size_t o0 = ((size_t)(b*SEQ + row0))*D_MODEL + h*DK;
    const size_t o1 = ((size_t)(b*SEQ + row1))*D_MODEL + h*DK;
    #pragma unroll
    for (int nb = 0; nb < 8; nb++) {
        const int col = nb*8 + tg*2;
        uint32_t H, L;
        split_pack2(oacc[nb][0]*inv0, oacc[nb][1]*inv0, H, L);
        *(uint32_t*)(g_ctxhi + o0 + col) = H;
        *(uint32_t*)(g_ctxlo + o0 + col) = L;
        split_pack2(oacc[nb][2]*inv1, oacc[nb][3]*inv1, H, L);
        *(uint32_t*)(g_ctxhi + o1 + col) = H;
        *(uint32_t*)(g_ctxlo + o1 + col) = L;
    }
}

// ---------------------------------------------------------------------------
extern "C" void kernel_launch(void* const* d_in, const int* in_sizes, int n_in,
                              void* d_out, int out_size)
{
    const float* x  = (const float*)d_in[0];
    const unsigned char* mask = (const unsigned char*)d_in[1];
    const float* Wq = (const float*)d_in[2];
    const float* bq = (const float*)d_in[3];
    const float* Wk = (const float*)d_in[4];
    const float* bk = (const float*)d_in[5];
    const float* Wv = (const float*)d_in[6];
    const float* bv = (const float*)d_in[7];
    const float* Wo = (const float*)d_in[8];
    const float* bo = (const float*)d_in[9];
    float* out = (float*)d_out;

    cudaFuncSetAttribute(attn_hmma_kernel,
                         cudaFuncAttributeMaxDynamicSharedMemorySize, ATTN_SMEM);

    split_x_kernel<<<M_ROWS*D_MODEL/4/256, 256>>>(x);
    split_w_kernel<<<dim3(D_MODEL*D_MODEL/4/256, 4), 256>>>(Wq, Wk, Wv, Wo);

    hmma_gemm_kernel<true><<<dim3(48, M_ROWS/128), 256>>>(bq, bk, bv, nullptr);

    attn_hmma_kernel<<<dim3(SEQ/128, NHEAD, BATCH), 256, ATTN_SMEM>>>(mask);

    hmma_gemm_kernel<false><<<dim3(16, M_ROWS/128), 256>>>(bo, bo, bo, out);
}

// round 9
// speedup vs baseline: 1.2890x; 1.1081x over previous
#include <cuda_runtime.h>
#include <cuda_bf16.h>
#include <math.h>
#include <stdint.h>

#define D_MODEL 1024
#define NHEAD   16
#define DK      64
#define BATCH   4
#define SEQ     2048
#define M_ROWS  (BATCH*SEQ)   // 8192
#define HQKV    (BATCH*NHEAD*SEQ*DK)

// Inter-kernel interchange: bf16 hi/lo pairs (value = hi+lo, err ~2^-18 rel)
__device__ __align__(16) __nv_bfloat16 g_xhi[M_ROWS*D_MODEL];
__device__ __align__(16) __nv_bfloat16 g_xlo[M_ROWS*D_MODEL];
__device__ __align__(16) __nv_bfloat16 g_Whi[4*D_MODEL*D_MODEL];   // q,k,v,o
__device__ __align__(16) __nv_bfloat16 g_Wlo[4*D_MODEL*D_MODEL];
__device__ __align__(16) __nv_bfloat16 g_Qhi[HQKV];  // [B,H,T,dk], pre-scaled 0.125
__device__ __align__(16) __nv_bfloat16 g_Qlo[HQKV];
__device__ __align__(16) __nv_bfloat16 g_Khi[HQKV];
__device__ __align__(16) __nv_bfloat16 g_Klo[HQKV];
__device__ __align__(16) __nv_bfloat16 g_Vhi[HQKV];
__device__ __align__(16) __nv_bfloat16 g_Vlo[HQKV];
__device__ __align__(16) __nv_bfloat16 g_ctxhi[M_ROWS*D_MODEL];
__device__ __align__(16) __nv_bfloat16 g_ctxlo[M_ROWS*D_MODEL];

// ---------------------------------------------------------------------------
__device__ __forceinline__ void ldmx4(uint32_t* r, uint32_t addr) {
    asm volatile("ldmatrix.sync.aligned.m8n8.x4.shared.b16 {%0,%1,%2,%3}, [%4];"
                 : "=r"(r[0]), "=r"(r[1]), "=r"(r[2]), "=r"(r[3]) : "r"(addr));
}
__device__ __forceinline__ void ldmx4t(uint32_t* r, uint32_t addr) {
    asm volatile("ldmatrix.sync.aligned.m8n8.x4.trans.shared.b16 {%0,%1,%2,%3}, [%4];"
                 : "=r"(r[0]), "=r"(r[1]), "=r"(r[2]), "=r"(r[3]) : "r"(addr));
}
__device__ __forceinline__ void mma_bf16(float* d, const uint32_t* a,
                                         uint32_t b0, uint32_t b1) {
    asm volatile(
        "mma.sync.aligned.m16n8k16.row.col.f32.bf16.bf16.f32 "
        "{%0,%1,%2,%3}, {%4,%5,%6,%7}, {%8,%9}, {%0,%1,%2,%3};"
        : "+f"(d[0]), "+f"(d[1]), "+f"(d[2]), "+f"(d[3])
        : "r"(a[0]), "r"(a[1]), "r"(a[2]), "r"(a[3]), "r"(b0), "r"(b1));
}
__device__ __forceinline__ uint32_t smem_u32(const void* p) {
    uint32_t a;
    asm("{ .reg .u64 t; cvta.to.shared.u64 t, %1; cvt.u32.u64 %0, t; }"
        : "=r"(a) : "l"(p));
    return a;
}
__device__ __forceinline__ void cp16(uint32_t saddr, const void* g) {
    asm volatile("cp.async.cg.shared.global [%0], [%1], 16;"
                 :: "r"(saddr), "l"(g) : "memory");
}
#define CP_COMMIT()   asm volatile("cp.async.commit_group;" ::: "memory")
#define CP_WAIT(n)    asm volatile("cp.async.wait_group %0;" :: "n"(n) : "memory")

__device__ __forceinline__ uint32_t sw128(uint32_t off) {
    return off ^ ((off >> 3) & 0x70);
}
__device__ __forceinline__ unsigned short bf16bits(float f) {
    __nv_bfloat16 h = __float2bfloat16_rn(f);
    return *reinterpret_cast<unsigned short*>(&h);
}
__device__ __forceinline__ void split4(float4 v, uint2& H, uint2& L) {
    __nv_bfloat16 hx = __float2bfloat16_rn(v.x);
    __nv_bfloat16 hy = __float2bfloat16_rn(v.y);
    __nv_bfloat16 hz = __float2bfloat16_rn(v.z);
    __nv_bfloat16 hw = __float2bfloat16_rn(v.w);
    __nv_bfloat162 h0 = __halves2bfloat162(hx, hy);
    __nv_bfloat162 h1 = __halves2bfloat162(hz, hw);
    __nv_bfloat16 lx = __float2bfloat16_rn(v.x - __bfloat162float(hx));
    __nv_bfloat16 ly = __float2bfloat16_rn(v.y - __bfloat162float(hy));
    __nv_bfloat16 lz = __float2bfloat16_rn(v.z - __bfloat162float(hz));
    __nv_bfloat16 lw = __float2bfloat16_rn(v.w - __bfloat162float(hw));
    __nv_bfloat162 l0 = __halves2bfloat162(lx, ly);
    __nv_bfloat162 l1 = __halves2bfloat162(lz, lw);
    H.x = *reinterpret_cast<uint32_t*>(&h0);
    H.y = *reinterpret_cast<uint32_t*>(&h1);
    L.x = *reinterpret_cast<uint32_t*>(&l0);
    L.y = *reinterpret_cast<uint32_t*>(&l1);
}
__device__ __forceinline__ void split_pack2(float a, float b, uint32_t& H, uint32_t& L) {
    unsigned short ha = bf16bits(a), hb = bf16bits(b);
    float fa, fb;
    { __nv_bfloat16 t = *reinterpret_cast<__nv_bfloat16*>(&ha); fa = __bfloat162float(t); }
    { __nv_bfloat16 t = *reinterpret_cast<__nv_bfloat16*>(&hb); fb = __bfloat162float(t); }
    unsigned short la = bf16bits(a - fa), lb = bf16bits(b - fb);
    H = (uint32_t)ha | ((uint32_t)hb << 16);
    L = (uint32_t)la | ((uint32_t)lb << 16);
}

// ---------------------------------------------------------------------------
// Pre-split kernels (memory-bound, one-shot)
// ---------------------------------------------------------------------------
__global__ __launch_bounds__(256) void split_x_kernel(const float* __restrict__ x) {
    const int i = blockIdx.x * 256 + threadIdx.x;
    float4 v = ((const float4*)x)[i];
    v.x += 1e-8f; v.y += 1e-8f; v.z += 1e-8f; v.w += 1e-8f;
    uint2 H, L;
    split4(v, H, L);
    ((uint2*)g_xhi)[i] = H;
    ((uint2*)g_xlo)[i] = L;
}

__global__ __launch_bounds__(256) void split_w_kernel(const float* __restrict__ W0,
                                                      const float* __restrict__ W1,
                                                      const float* __restrict__ W2,
                                                      const float* __restrict__ W3) {
    const int which = blockIdx.y;
    const float* W = which == 0 ? W0 : which == 1 ? W1 : which == 2 ? W2 : W3;
    const int i = blockIdx.x * 256 + threadIdx.x;
    float4 v = ((const float4*)W)[i];
    uint2 H, L;
    split4(v, H, L);
    const size_t o = (size_t)which * (D_MODEL*D_MODEL/4) + i;
    ((uint2*)g_Whi)[o] = H;
    ((uint2*)g_Wlo)[o] = L;
}

// ---------------------------------------------------------------------------
// HMMA GEMM v2: bf16 hi/lo inputs, cp.async double-buffered tiles.
// Dynamic smem 96KB = 2 x {Ahi@0(16K), Alo@16K, Bhi@32K(8K), Blo@40K}.
// CTA tile M=128, N=64, Kchunk=64; 8 warps 4(M)x2(N), warp tile 32x32.
// ---------------------------------------------------------------------------
#define GEMM_BUF   49152
#define GEMM_SMEM  (2*GEMM_BUF)

template<bool QKV>
__global__ __launch_bounds__(256)
void hmma_gemm_kernel(const float* __restrict__ b0v,
                      const float* __restrict__ b1v,
                      const float* __restrict__ b2v,
                      float* __restrict__ outp)
{
    extern __shared__ __align__(1024) unsigned char gsm[];

    const int tid  = threadIdx.x;
    const int wid  = tid >> 5;
    const int lane = tid & 31;
    const int mw   = wid & 3;
    const int nw   = wid >> 2;

    const int bx    = blockIdx.x;
    const int which = QKV ? (bx >> 4) : 3;
    const int n0    = (bx & 15) * 64;
    const int m0    = blockIdx.y * 128;

    const __nv_bfloat16* Ahi = QKV ? g_xhi : g_ctxhi;
    const __nv_bfloat16* Alo = QKV ? g_xlo : g_ctxlo;
    const __nv_bfloat16* Whi = g_Whi + (size_t)which * D_MODEL * D_MODEL;
    const __nv_bfloat16* Wlo = g_Wlo + (size_t)which * D_MODEL * D_MODEL;
    const float* bias = QKV ? (which == 0 ? b0v : which == 1 ? b1v : b2v) : b0v;

    const uint32_t sb = smem_u32(gsm);

    const int blk      = lane >> 3;
    const int rr       = lane & 7;
    const int aRowHalf = blk & 1;
    const int aKHalf   = blk >> 1;
    const int bNb      = blk >> 1;
    const int bKHalf   = blk & 1;

    // Per-thread fill addressing: A = 128 rows x 8 cols of 16B (4 iters),
    // B = 64 rows x 8 cols (2 iters). Row base for A-iter i: tid>>3 + i*32.
    const int frow = tid >> 3;             // 0..31
    const int fcol = tid & 7;              // 0..7
    uint32_t swA[4], swB[2];
    #pragma unroll
    for (int i = 0; i < 4; i++)
        swA[i] = sw128((uint32_t)((frow + i*32) * 128 + fcol * 16));
    swB[0] = swA[0];
    swB[1] = swA[1];

    float acc[2][4][4];
    #pragma unroll
    for (int i=0;i<2;i++)
        #pragma unroll
        for (int j=0;j<4;j++)
            #pragma unroll
            for (int l=0;l<4;l++) acc[i][j][l]=0.f;

    // Prologue: async-load chunk 0 into buffer 0
    {
        #pragma unroll
        for (int i = 0; i < 4; i++) {
            const size_t go = (size_t)(m0 + frow + i*32) * D_MODEL + fcol * 8;
            cp16(sb + swA[i],         Ahi + go);
            cp16(sb + 16384 + swA[i], Alo + go);
        }
        #pragma unroll
        for (int i = 0; i < 2; i++) {
            const size_t go = (size_t)(n0 + frow + i*32) * D_MODEL + fcol * 8;
            cp16(sb + 32768 + swB[i], Whi + go);
            cp16(sb + 40960 + swB[i], Wlo + go);
        }
        CP_COMMIT();
    }

    for (int chunk = 0; chunk < 16; chunk++) {
        const uint32_t cbuf = (uint32_t)(chunk & 1) * GEMM_BUF;

        if (chunk + 1 < 16) {
            const uint32_t nbuf = (uint32_t)((chunk + 1) & 1) * GEMM_BUF;
            const int k1 = (chunk + 1) * 64;
            #pragma unroll
            for (int i = 0; i < 4; i++) {
                const size_t go = (size_t)(m0 + frow + i*32) * D_MODEL + k1 + fcol * 8;
                cp16(sb + nbuf + swA[i],         Ahi + go);
                cp16(sb + nbuf + 16384 + swA[i], Alo + go);
            }
            #pragma unroll
            for (int i = 0; i < 2; i++) {
                const size_t go = (size_t)(n0 + frow + i*32) * D_MODEL + k1 + fcol * 8;
                cp16(sb + nbuf + 32768 + swB[i], Whi + go);
                cp16(sb + nbuf + 40960 + swB[i], Wlo + go);
            }
            CP_COMMIT();
            CP_WAIT(1);
        } else {
            CP_WAIT(0);
        }
        __syncthreads();

        #pragma unroll
        for (int ks = 0; ks < 4; ks++) {
            uint32_t ah[2][4], al[2][4];
            #pragma unroll
            for (int mf = 0; mf < 2; mf++) {
                const uint32_t row = (uint32_t)(mw*32 + mf*16 + aRowHalf*8 + rr);
                const uint32_t off = sw128(row * 128 + (uint32_t)(ks*16 + aKHalf*8) * 2);
                ldmx4(ah[mf], sb + cbuf + off);
                ldmx4(al[mf], sb + cbuf + 16384 + off);
            }
            uint32_t bh[2][4], bl[2][4];
            #pragma unroll
            for (int pr = 0; pr < 2; pr++) {
                const uint32_t n   = (uint32_t)(nw*32 + pr*16 + bNb*8 + rr);
                const uint32_t off = sw128(n * 128 + (uint32_t)(ks*16 + bKHalf*8) * 2);
                ldmx4(bh[pr], sb + cbuf + 32768 + off);
                ldmx4(bl[pr], sb + cbuf + 40960 + off);
            }
            #pragma unroll
            for (int mf = 0; mf < 2; mf++) {
                #pragma unroll
                for (int nb = 0; nb < 4; nb++) {
                    const uint32_t B0h = bh[nb>>1][(nb&1)*2+0];
                    const uint32_t B1h = bh[nb>>1][(nb&1)*2+1];
                    const uint32_t B0l = bl[nb>>1][(nb&1)*2+0];
                    const uint32_t B1l = bl[nb>>1][(nb&1)*2+1];
                    mma_bf16(acc[mf][nb], ah[mf], B0h, B1h);
                    mma_bf16(acc[mf][nb], ah[mf], B0l, B1l);
                    mma_bf16(acc[mf][nb], al[mf], B0h, B1h);
                }
            }
        }
        __syncthreads();   // buffer consumed before chunk+2 overwrites it
    }

    const int gID = lane >> 2;
    const int tg  = lane & 3;

    #pragma unroll
    for (int mf = 0; mf < 2; mf++) {
        #pragma unroll
        for (int nb = 0; nb < 4; nb++) {
            const int colL = nw*32 + nb*8 + tg*2;
            const float bb0 = bias[n0 + colL];
            const float bb1 = bias[n0 + colL + 1];
            #pragma unroll
            for (int half = 0; half < 2; half++) {
                const int m = m0 + mw*32 + mf*16 + half*8 + gID;
                if (QKV && which < 3) {
                    float v0 = fminf(fmaxf(acc[mf][nb][half*2+0] + bb0, -10.f), 10.f);
                    float v1 = fminf(fmaxf(acc[mf][nb][half*2+1] + bb1, -10.f), 10.f);
                    if (which == 0) { v0 *= 0.125f; v1 *= 0.125f; }
                    uint32_t H, L;
                    split_pack2(v0, v1, H, L);
                    const int b_ = m >> 11;
                    const int t  = m & (SEQ - 1);
                    const int h  = bx & 15;
                    const size_t o = (((size_t)(b_*NHEAD + h))*SEQ + t)*DK + colL;
                    __nv_bfloat16* dh = (which == 0) ? g_Qhi : (which == 1) ? g_Khi : g_Vhi;
                    __nv_bfloat16* dl = (which == 0) ? g_Qlo : (which == 1) ? g_Klo : g_Vlo;
                    *(uint32_t*)(dh + o) = H;
                    *(uint32_t*)(dl + o) = L;
                } else {
                    float2 v;
                    v.x = fminf(fmaxf(acc[mf][nb][half*2+0] + bb0, -100.f), 100.f);
                    v.y = fminf(fmaxf(acc[mf][nb][half*2+1] + bb1, -100.f), 100.f);
                    *(float2*)(outp + (size_t)m * D_MODEL + n0 + colL) = v;
                }
            }
        }
    }
}

// ---------------------------------------------------------------------------
// HMMA flash attention v3 (unchanged from R8: 514us, tensor 65.8%).
// ---------------------------------------------------------------------------
#define ATTN_SMEM 65536
#define NT (SEQ/64)

__global__ __launch_bounds__(256, 1)
void attn_hmma_kernel(const unsigned char* __restrict__ mask)
{
    extern __shared__ __align__(1024) unsigned char sbuf[];
    __shared__ unsigned char smask[64];

    const int tid  = threadIdx.x;
    const int wid  = tid >> 5;
    const int lane = tid & 31;
    const int gID  = lane >> 2;
    const int tg   = lane & 3;

    const int blk      = lane >> 3;
    const int rr       = lane & 7;
    const int aRowHalf = blk & 1;
    const int aKHalf   = blk >> 1;
    const int bNb      = blk >> 1;
    const int bKHalf   = blk & 1;

    const int vKey = lane & 15;
    const int vDh  = lane >> 4;

    const int qt = blockIdx.x;
    const int h  = blockIdx.y;
    const int b  = blockIdx.z;
    const int m0 = qt * 128;

    const size_t headoff = ((size_t)(b*NHEAD + h))*SEQ*DK;
    const __nv_bfloat16* Qhi = g_Qhi + headoff;
    const __nv_bfloat16* Qlo = g_Qlo + headoff;
    const __nv_bfloat16* Khi = g_Khi + headoff;
    const __nv_bfloat16* Klo = g_Klo + headoff;
    const __nv_bfloat16* Vhi = g_Vhi + headoff;
    const __nv_bfloat16* Vlo = g_Vlo + headoff;
    const unsigned char* mb = mask + (size_t)b*SEQ;

    const uint32_t sb = smem_u32(sbuf);

    const int frow0 = tid >> 3;
    const int fcol  = tid & 7;
    const uint32_t swf0 = sw128((uint32_t)(frow0 * 128 + fcol * 16));
    const uint32_t swf1 = sw128((uint32_t)((frow0 + 32) * 128 + fcol * 16));

    #pragma unroll
    for (int i = 0; i < 4; i++) {
        const int f   = tid + i * 256;
        const int row = f >> 3;
        const int c   = f & 7;
        const size_t go = (size_t)(m0 + row) * DK + c * 8;
        const uint32_t sw = sw128((uint32_t)(row * 128 + c * 16));
        *(uint4*)(sbuf + sw)         = *(const uint4*)(Qhi + go);
        *(uint4*)(sbuf + 16384 + sw) = *(const uint4*)(Qlo + go);
    }
    __syncthreads();

    uint32_t qh[4][4], ql[4][4];
    #pragma unroll
    for (int ks = 0; ks < 4; ks++) {
        const uint32_t row = (uint32_t)(wid*16 + aRowHalf*8 + rr);
        const uint32_t off = sw128(row * 128 + (uint32_t)(ks*16 + aKHalf*8) * 2);
        ldmx4(qh[ks], sb + off);
        ldmx4(ql[ks], sb + 16384 + off);
    }
    __syncthreads();

    float oacc[8][4];
    #pragma unroll
    for (int nb = 0; nb < 8; nb++)
        #pragma unroll
        for (int i = 0; i < 4; i++) oacc[nb][i] = 0.f;
    float lrun0 = 0.f, lrun1 = 0.f;

    {
        const size_t g0 = (size_t)frow0 * DK + fcol * 8;
        const size_t g1 = (size_t)(frow0 + 32) * DK + fcol * 8;
        cp16(sb + swf0,         Khi + g0);  cp16(sb + swf1,         Khi + g1);
        cp16(sb +  8192 + swf0, Klo + g0);  cp16(sb +  8192 + swf1, Klo + g1);
        cp16(sb + 16384 + swf0, Vhi + g0);  cp16(sb + 16384 + swf1, Vhi + g1);
        cp16(sb + 24576 + swf0, Vlo + g0);  cp16(sb + 24576 + swf1, Vlo + g1);
        CP_COMMIT();
    }

    for (int t = 0; t < NT; t++) {
        const int kt = t * 64;
        const uint32_t cbuf = (uint32_t)(t & 1) * 32768;

        if (tid < 16) ((uint32_t*)smask)[tid] = *(const uint32_t*)(mb + kt + tid*4);

        if (t + 1 < NT) {
            const uint32_t nbuf = (uint32_t)((t + 1) & 1) * 32768;
            const size_t base = (size_t)(kt + 64) * DK;
            const size_t g0 = base + (size_t)frow0 * DK + fcol * 8;
            const size_t g1 = base + (size_t)(frow0 + 32) * DK + fcol * 8;
            cp16(sb + nbuf + swf0,         Khi + g0);  cp16(sb + nbuf + swf1,         Khi + g1);
            cp16(sb + nbuf +  8192 + swf0, Klo + g0);  cp16(sb + nbuf +  8192 + swf1, Klo + g1);
            cp16(sb + nbuf + 16384 + swf0, Vhi + g0);  cp16(sb + nbuf + 16384 + swf1, Vhi + g1);
            cp16(sb + nbuf + 24576 + swf0, Vlo + g0);  cp16(sb + nbuf + 24576 + swf1, Vlo + g1);
            CP_COMMIT();
            CP_WAIT(1);
        } else {
            CP_WAIT(0);
        }
        __syncthreads();

        float sacc[8][4];
        #pragma unroll
        for (int nt = 0; nt < 8; nt++)
            #pragma unroll
            for (int i = 0; i < 4; i++) sacc[nt][i] = 0.f;

        #pragma unroll
        for (int ks = 0; ks < 4; ks++) {
            #pragma unroll
            for (int kg = 0; kg < 4; kg++) {
                uint32_t bh[4], bl[4];
                const uint32_t row = (uint32_t)(kg*16 + bNb*8 + rr);
                const uint32_t off = sw128(row * 128 + (uint32_t)(ks*16 + bKHalf*8) * 2);
                ldmx4(bh, sb + cbuf + off);
                ldmx4(bl, sb + cbuf + 8192 + off);
                #pragma unroll
                for (int sub = 0; sub < 2; sub++) {
                    const int nt = kg*2 + sub;
                    mma_bf16(sacc[nt], qh[ks], bh[sub*2], bh[sub*2+1]);
                    mma_bf16(sacc[nt], qh[ks], bl[sub*2], bl[sub*2+1]);
                    mma_bf16(sacc[nt], ql[ks], bh[sub*2], bh[sub*2+1]);
                }
            }
        }

        uint32_t pah[4][4], pal[4][4];
        float rs0 = 0.f, rs1 = 0.f;
        #pragma unroll
        for (int nt = 0; nt < 8; nt++) {
            const int keyc = nt*8 + tg*2;
            const bool f0 = smask[keyc] != 0;
            const bool f1 = smask[keyc + 1] != 0;
            float s0 = fminf(fmaxf(sacc[nt][0], -50.f), 50.f); if (f0) s0 = -10000.f;
            float s1 = fminf(fmaxf(sacc[nt][1], -50.f), 50.f); if (f1) s1 = -10000.f;
            float s2 = fminf(fmaxf(sacc[nt][2], -50.f), 50.f); if (f0) s2 = -10000.f;
            float s3 = fminf(fmaxf(sacc[nt][3], -50.f), 50.f); if (f1) s3 = -10000.f;
            const float p0 = __expf(s0);
            const float p1 = __expf(s1);
            const float p2 = __expf(s2);
            const float p3 = __expf(s3);
            rs0 += p0 + p1;
            rs1 += p2 + p3;
            const int ks  = nt >> 1;
            const int sub = nt & 1;
            split_pack2(p0, p1, pah[ks][sub*2+0], pal[ks][sub*2+0]);
            split_pack2(p2, p3, pah[ks][sub*2+1], pal[ks][sub*2+1]);
        }
        rs0 += __shfl_xor_sync(0xffffffffu, rs0, 1);
        rs0 += __shfl_xor_sync(0xffffffffu, rs0, 2);
        rs1 += __shfl_xor_sync(0xffffffffu, rs1, 1);
        rs1 += __shfl_xor_sync(0xffffffffu, rs1, 2);
        lrun0 += rs0;
        lrun1 += rs1;

        #pragma unroll
        for (int ks = 0; ks < 4; ks++) {
            #pragma unroll
            for (int dg = 0; dg < 4; dg++) {
                uint32_t vh[4], vl[4];
                const uint32_t key = (uint32_t)(ks*16 + vKey);
                const uint32_t off = sw128(key * 128 + (uint32_t)(dg*16 + vDh*8) * 2);
                ldmx4t(vh, sb + cbuf + 16384 + off);
                ldmx4t(vl, sb + cbuf + 24576 + off);
                #pragma unroll
                for (int sub = 0; sub < 2; sub++) {
                    const int nb = dg*2 + sub;
                    mma_bf16(oacc[nb], pah[ks], vh[sub*2], vh[sub*2+1]);
                    mma_bf16(oacc[nb], pah[ks], vl[sub*2], vl[sub*2+1]);
                    mma_bf16(oacc[nb], pal[ks], vh[sub*2], vh[sub*2+1]);
                }
            }
        }
        __syncthreads();
    }

    const float inv0 = 1.f / lrun0;
    const float inv1 = 1.f / lrun1;
    const int row0 = m0 + wid*16 + gID;
    const int row1 = row0 + 8;
    const size_t o0 = ((size_t)(b*SEQ + row0))*D_MODEL + h*DK;
    const size_t o1 = ((size_t)(b*SEQ + row1))*D_MODEL + h*DK;
    #pragma unroll
    for (int nb = 0; nb < 8; nb++) {
        const int col = nb*8 + tg*2;
        uint32_t H, L;
        split_pack2(oacc[nb][0]*inv0, oacc[nb][1]*inv0, H, L);
        *(uint32_t*)(g_ctxhi + o0 + col) = H;
        *(uint32_t*)(g_ctxlo + o0 + col) = L;
        split_pack2(oacc[nb][2]*inv1, oacc[nb][3]*inv1, H, L);
        *(uint32_t*)(g_ctxhi + o1 + col) = H;
        *(uint32_t*)(g_ctxlo + o1 + col) = L;
    }
}

// ---------------------------------------------------------------------------
extern "C" void kernel_launch(void* const* d_in, const int* in_sizes, int n_in,
                              void* d_out, int out_size)
{
    const float* x  = (const float*)d_in[0];
    const unsigned char* mask = (const unsigned char*)d_in[1];
    const float* Wq = (const float*)d_in[2];
    const float* bq = (const float*)d_in[3];
    const float* Wk = (const float*)d_in[4];
    const float* bk = (const float*)d_in[5];
    const float* Wv = (const float*)d_in[6];
    const float* bv = (const float*)d_in[7];
    const float* Wo = (const float*)d_in[8];
    const float* bo = (const float*)d_in[9];
    float* out = (float*)d_out;

    cudaFuncSetAttribute(attn_hmma_kernel,
                         cudaFuncAttributeMaxDynamicSharedMemorySize, ATTN_SMEM);
    cudaFuncSetAttribute(hmma_gemm_kernel<true>,
                         cudaFuncAttributeMaxDynamicSharedMemorySize, GEMM_SMEM);
    cudaFuncSetAttribute(hmma_gemm_kernel<false>,
                         cudaFuncAttributeMaxDynamicSharedMemorySize, GEMM_SMEM);

    split_x_kernel<<<M_ROWS*D_MODEL/4/256, 256>>>(x);
    split_w_kernel<<<dim3(D_MODEL*D_MODEL/4/256, 4), 256>>>(Wq, Wk, Wv, Wo);

    hmma_gemm_kernel<true><<<dim3(48, M_ROWS/128), 256, GEMM_SMEM>>>(bq, bk, bv, nullptr);

    attn_hmma_kernel<<<dim3(SEQ/128, NHEAD, BATCH), 256, ATTN_SMEM>>>(mask);

    hmma_gemm_kernel<false><<<dim3(16, M_ROWS/128), 256, GEMM_SMEM>>>(bo, bo, bo, out);
}

// round 10
// speedup vs baseline: 1.3098x; 1.0162x over previous
#include <cuda_runtime.h>
#include <cuda_bf16.h>
#include <math.h>
#include <stdint.h>

#define D_MODEL 1024
#define NHEAD   16
#define DK      64
#define BATCH   4
#define SEQ     2048
#define M_ROWS  (BATCH*SEQ)   // 8192
#define HQKV    (BATCH*NHEAD*SEQ*DK)

// log2(e) folded constants
#define Q_PRESCALE 0.18033688011112042f   // 0.125 * log2(e)
#define CLIP_LOG2  72.13475204444817f     // 50 * log2(e)
#define MASKED_S   (-14427.0f)            // exp2 -> 0

// Inter-kernel interchange: bf16 hi/lo pairs (value = hi+lo, err ~2^-18 rel)
__device__ __align__(16) __nv_bfloat16 g_xhi[M_ROWS*D_MODEL];
__device__ __align__(16) __nv_bfloat16 g_xlo[M_ROWS*D_MODEL];
__device__ __align__(16) __nv_bfloat16 g_Whi[4*D_MODEL*D_MODEL];   // q,k,v,o
__device__ __align__(16) __nv_bfloat16 g_Wlo[4*D_MODEL*D_MODEL];
__device__ __align__(16) __nv_bfloat16 g_Qhi[HQKV];  // pre-scaled by 0.125*log2e
__device__ __align__(16) __nv_bfloat16 g_Qlo[HQKV];
__device__ __align__(16) __nv_bfloat16 g_Khi[HQKV];
__device__ __align__(16) __nv_bfloat16 g_Klo[HQKV];
__device__ __align__(16) __nv_bfloat16 g_Vhi[HQKV];
__device__ __align__(16) __nv_bfloat16 g_Vlo[HQKV];
__device__ __align__(16) __nv_bfloat16 g_ctxhi[M_ROWS*D_MODEL];
__device__ __align__(16) __nv_bfloat16 g_ctxlo[M_ROWS*D_MODEL];

// ---------------------------------------------------------------------------
__device__ __forceinline__ void ldmx4(uint32_t* r, uint32_t addr) {
    asm volatile("ldmatrix.sync.aligned.m8n8.x4.shared.b16 {%0,%1,%2,%3}, [%4];"
                 : "=r"(r[0]), "=r"(r[1]), "=r"(r[2]), "=r"(r[3]) : "r"(addr));
}
__device__ __forceinline__ void ldmx4t(uint32_t* r, uint32_t addr) {
    asm volatile("ldmatrix.sync.aligned.m8n8.x4.trans.shared.b16 {%0,%1,%2,%3}, [%4];"
                 : "=r"(r[0]), "=r"(r[1]), "=r"(r[2]), "=r"(r[3]) : "r"(addr));
}
__device__ __forceinline__ void mma_bf16(float* d, const uint32_t* a,
                                         uint32_t b0, uint32_t b1) {
    asm volatile(
        "mma.sync.aligned.m16n8k16.row.col.f32.bf16.bf16.f32 "
        "{%0,%1,%2,%3}, {%4,%5,%6,%7}, {%8,%9}, {%0,%1,%2,%3};"
        : "+f"(d[0]), "+f"(d[1]), "+f"(d[2]), "+f"(d[3])
        : "r"(a[0]), "r"(a[1]), "r"(a[2]), "r"(a[3]), "r"(b0), "r"(b1));
}
__device__ __forceinline__ uint32_t smem_u32(const void* p) {
    uint32_t a;
    asm("{ .reg .u64 t; cvta.to.shared.u64 t, %1; cvt.u32.u64 %0, t; }"
        : "=r"(a) : "l"(p));
    return a;
}
__device__ __forceinline__ void cp16(uint32_t saddr, const void* g) {
    asm volatile("cp.async.cg.shared.global [%0], [%1], 16;"
                 :: "r"(saddr), "l"(g) : "memory");
}
#define CP_COMMIT()   asm volatile("cp.async.commit_group;" ::: "memory")
#define CP_WAIT(n)    asm volatile("cp.async.wait_group %0;" :: "n"(n) : "memory")

__device__ __forceinline__ uint32_t sw128(uint32_t off) {
    return off ^ ((off >> 3) & 0x70);
}
__device__ __forceinline__ float ex2(float x) {
    float y;
    asm("ex2.approx.f32 %0, %1;" : "=f"(y) : "f"(x));
    return y;
}
__device__ __forceinline__ void split4(float4 v, uint2& H, uint2& L) {
    __nv_bfloat162 h0 = __floats2bfloat162_rn(v.x, v.y);
    __nv_bfloat162 h1 = __floats2bfloat162_rn(v.z, v.w);
    H.x = *reinterpret_cast<uint32_t*>(&h0);
    H.y = *reinterpret_cast<uint32_t*>(&h1);
    float rx = v.x - __uint_as_float(H.x << 16);
    float ry = v.y - __uint_as_float(H.x & 0xFFFF0000u);
    float rz = v.z - __uint_as_float(H.y << 16);
    float rw = v.w - __uint_as_float(H.y & 0xFFFF0000u);
    __nv_bfloat162 l0 = __floats2bfloat162_rn(rx, ry);
    __nv_bfloat162 l1 = __floats2bfloat162_rn(rz, rw);
    L.x = *reinterpret_cast<uint32_t*>(&l0);
    L.y = *reinterpret_cast<uint32_t*>(&l1);
}
// pack (a,b) -> bf16x2 hi word + bf16x2 lo-residual word (packed cvt path)
__device__ __forceinline__ void split_pack2(float a, float b, uint32_t& H, uint32_t& L) {
    __nv_bfloat162 h2 = __floats2bfloat162_rn(a, b);
    H = *reinterpret_cast<uint32_t*>(&h2);
    float fa = __uint_as_float(H << 16);
    float fb = __uint_as_float(H & 0xFFFF0000u);
    __nv_bfloat162 l2 = __floats2bfloat162_rn(a - fa, b - fb);
    L = *reinterpret_cast<uint32_t*>(&l2);
}

// ---------------------------------------------------------------------------
// Pre-split kernels (memory-bound, one-shot)
// ---------------------------------------------------------------------------
__global__ __launch_bounds__(256) void split_x_kernel(const float* __restrict__ x) {
    const int i = blockIdx.x * 256 + threadIdx.x;
    float4 v = ((const float4*)x)[i];
    v.x += 1e-8f; v.y += 1e-8f; v.z += 1e-8f; v.w += 1e-8f;
    uint2 H, L;
    split4(v, H, L);
    ((uint2*)g_xhi)[i] = H;
    ((uint2*)g_xlo)[i] = L;
}

__global__ __launch_bounds__(256) void split_w_kernel(const float* __restrict__ W0,
                                                      const float* __restrict__ W1,
                                                      const float* __restrict__ W2,
                                                      const float* __restrict__ W3) {
    const int which = blockIdx.y;
    const float* W = which == 0 ? W0 : which == 1 ? W1 : which == 2 ? W2 : W3;
    const int i = blockIdx.x * 256 + threadIdx.x;
    float4 v = ((const float4*)W)[i];
    uint2 H, L;
    split4(v, H, L);
    const size_t o = (size_t)which * (D_MODEL*D_MODEL/4) + i;
    ((uint2*)g_Whi)[o] = H;
    ((uint2*)g_Wlo)[o] = L;
}

// ---------------------------------------------------------------------------
// HMMA GEMM v3: cp.async double-buffered + 3-pass MMA ordering (RAW dist 8).
// Dynamic smem 96KB = 2 x {Ahi@0(16K), Alo@16K, Bhi@32K(8K), Blo@40K}.
// ---------------------------------------------------------------------------
#define GEMM_BUF   49152
#define GEMM_SMEM  (2*GEMM_BUF)

template<bool QKV>
__global__ __launch_bounds__(256)
void hmma_gemm_kernel(const float* __restrict__ b0v,
                      const float* __restrict__ b1v,
                      const float* __restrict__ b2v,
                      float* __restrict__ outp)
{
    extern __shared__ __align__(1024) unsigned char gsm[];

    const int tid  = threadIdx.x;
    const int wid  = tid >> 5;
    const int lane = tid & 31;
    const int mw   = wid & 3;
    const int nw   = wid >> 2;

    const int bx    = blockIdx.x;
    const int which = QKV ? (bx >> 4) : 3;
    const int n0    = (bx & 15) * 64;
    const int m0    = blockIdx.y * 128;

    const __nv_bfloat16* Ahi = QKV ? g_xhi : g_ctxhi;
    const __nv_bfloat16* Alo = QKV ? g_xlo : g_ctxlo;
    const __nv_bfloat16* Whi = g_Whi + (size_t)which * D_MODEL * D_MODEL;
    const __nv_bfloat16* Wlo = g_Wlo + (size_t)which * D_MODEL * D_MODEL;
    const float* bias = QKV ? (which == 0 ? b0v : which == 1 ? b1v : b2v) : b0v;

    const uint32_t sb = smem_u32(gsm);

    const int blk      = lane >> 3;
    const int rr       = lane & 7;
    const int aRowHalf = blk & 1;
    const int aKHalf   = blk >> 1;
    const int bNb      = blk >> 1;
    const int bKHalf   = blk & 1;

    const int frow = tid >> 3;
    const int fcol = tid & 7;
    uint32_t swA[4], swB[2];
    #pragma unroll
    for (int i = 0; i < 4; i++)
        swA[i] = sw128((uint32_t)((frow + i*32) * 128 + fcol * 16));
    swB[0] = swA[0];
    swB[1] = swA[1];

    float acc[2][4][4];
    #pragma unroll
    for (int i=0;i<2;i++)
        #pragma unroll
        for (int j=0;j<4;j++)
            #pragma unroll
            for (int l=0;l<4;l++) acc[i][j][l]=0.f;

    {
        #pragma unroll
        for (int i = 0; i < 4; i++) {
            const size_t go = (size_t)(m0 + frow + i*32) * D_MODEL + fcol * 8;
            cp16(sb + swA[i],         Ahi + go);
            cp16(sb + 16384 + swA[i], Alo + go);
        }
        #pragma unroll
        for (int i = 0; i < 2; i++) {
            const size_t go = (size_t)(n0 + frow + i*32) * D_MODEL + fcol * 8;
            cp16(sb + 32768 + swB[i], Whi + go);
            cp16(sb + 40960 + swB[i], Wlo + go);
        }
        CP_COMMIT();
    }

    for (int chunk = 0; chunk < 16; chunk++) {
        const uint32_t cbuf = (uint32_t)(chunk & 1) * GEMM_BUF;

        if (chunk + 1 < 16) {
            const uint32_t nbuf = (uint32_t)((chunk + 1) & 1) * GEMM_BUF;
            const int k1 = (chunk + 1) * 64;
            #pragma unroll
            for (int i = 0; i < 4; i++) {
                const size_t go = (size_t)(m0 + frow + i*32) * D_MODEL + k1 + fcol * 8;
                cp16(sb + nbuf + swA[i],         Ahi + go);
                cp16(sb + nbuf + 16384 + swA[i], Alo + go);
            }
            #pragma unroll
            for (int i = 0; i < 2; i++) {
                const size_t go = (size_t)(n0 + frow + i*32) * D_MODEL + k1 + fcol * 8;
                cp16(sb + nbuf + 32768 + swB[i], Whi + go);
                cp16(sb + nbuf + 40960 + swB[i], Wlo + go);
            }
            CP_COMMIT();
            CP_WAIT(1);
        } else {
            CP_WAIT(0);
        }
        __syncthreads();

        #pragma unroll
        for (int ks = 0; ks < 4; ks++) {
            uint32_t ah[2][4], al[2][4];
            #pragma unroll
            for (int mf = 0; mf < 2; mf++) {
                const uint32_t row = (uint32_t)(mw*32 + mf*16 + aRowHalf*8 + rr);
                const uint32_t off = sw128(row * 128 + (uint32_t)(ks*16 + aKHalf*8) * 2);
                ldmx4(ah[mf], sb + cbuf + off);
                ldmx4(al[mf], sb + cbuf + 16384 + off);
            }
            uint32_t bh[2][4], bl[2][4];
            #pragma unroll
            for (int pr = 0; pr < 2; pr++) {
                const uint32_t n   = (uint32_t)(nw*32 + pr*16 + bNb*8 + rr);
                const uint32_t off = sw128(n * 128 + (uint32_t)(ks*16 + bKHalf*8) * 2);
                ldmx4(bh[pr], sb + cbuf + 32768 + off);
                ldmx4(bl[pr], sb + cbuf + 40960 + off);
            }
            // 3 passes over 8 accumulators: RAW reuse distance 8
            #pragma unroll
            for (int mf = 0; mf < 2; mf++)
                #pragma unroll
                for (int nb = 0; nb < 4; nb++)
                    mma_bf16(acc[mf][nb], ah[mf], bh[nb>>1][(nb&1)*2], bh[nb>>1][(nb&1)*2+1]);
            #pragma unroll
            for (int mf = 0; mf < 2; mf++)
                #pragma unroll
                for (int nb = 0; nb < 4; nb++)
                    mma_bf16(acc[mf][nb], ah[mf], bl[nb>>1][(nb&1)*2], bl[nb>>1][(nb&1)*2+1]);
            #pragma unroll
            for (int mf = 0; mf < 2; mf++)
                #pragma unroll
                for (int nb = 0; nb < 4; nb++)
                    mma_bf16(acc[mf][nb], al[mf], bh[nb>>1][(nb&1)*2], bh[nb>>1][(nb&1)*2+1]);
        }
        __syncthreads();
    }

    const int gID = lane >> 2;
    const int tg  = lane & 3;

    #pragma unroll
    for (int mf = 0; mf < 2; mf++) {
        #pragma unroll
        for (int nb = 0; nb < 4; nb++) {
            const int colL = nw*32 + nb*8 + tg*2;
            const float bb0 = bias[n0 + colL];
            const float bb1 = bias[n0 + colL + 1];
            #pragma unroll
            for (int half = 0; half < 2; half++) {
                const int m = m0 + mw*32 + mf*16 + half*8 + gID;
                if (QKV && which < 3) {
                    float v0 = fminf(fmaxf(acc[mf][nb][half*2+0] + bb0, -10.f), 10.f);
                    float v1 = fminf(fmaxf(acc[mf][nb][half*2+1] + bb1, -10.f), 10.f);
                    if (which == 0) { v0 *= Q_PRESCALE; v1 *= Q_PRESCALE; }
                    uint32_t H, L;
                    split_pack2(v0, v1, H, L);
                    const int b_ = m >> 11;
                    const int t  = m & (SEQ - 1);
                    const int h  = bx & 15;
                    const size_t o = (((size_t)(b_*NHEAD + h))*SEQ + t)*DK + colL;
                    __nv_bfloat16* dh = (which == 0) ? g_Qhi : (which == 1) ? g_Khi : g_Vhi;
                    __nv_bfloat16* dl = (which == 0) ? g_Qlo : (which == 1) ? g_Klo : g_Vlo;
                    *(uint32_t*)(dh + o) = H;
                    *(uint32_t*)(dl + o) = L;
                } else {
                    float2 v;
                    v.x = fminf(fmaxf(acc[mf][nb][half*2+0] + bb0, -100.f), 100.f);
                    v.y = fminf(fmaxf(acc[mf][nb][half*2+1] + bb1, -100.f), 100.f);
                    *(float2*)(outp + (size_t)m * D_MODEL + n0 + colL) = v;
                }
            }
        }
    }
}

// ---------------------------------------------------------------------------
// HMMA flash attention v4: cp.async double-buffered + 3-pass MMA ordering +
// exp2-domain softmax (Q pre-scaled by 0.125*log2e; clip +-50*log2e; single
// ex2.approx per score) + packed-cvt P splitting.
// ---------------------------------------------------------------------------
#define ATTN_SMEM 65536
#define NT (SEQ/64)

__global__ __launch_bounds__(256, 1)
void attn_hmma_kernel(const unsigned char* __restrict__ mask)
{
    extern __shared__ __align__(1024) unsigned char sbuf[];
    __shared__ unsigned char smask[64];

    const int tid  = threadIdx.x;
    const int wid  = tid >> 5;
    const int lane = tid & 31;
    const int gID  = lane >> 2;
    const int tg   = lane & 3;

    const int blk      = lane >> 3;
    const int rr       = lane & 7;
    const int aRowHalf = blk & 1;
    const int aKHalf   = blk >> 1;
    const int bNb      = blk >> 1;
    const int bKHalf   = blk & 1;

    const int vKey = lane & 15;
    const int vDh  = lane >> 4;

    const int qt = blockIdx.x;
    const int h  = blockIdx.y;
    const int b  = blockIdx.z;
    const int m0 = qt * 128;

    const size_t headoff = ((size_t)(b*NHEAD + h))*SEQ*DK;
    const __nv_bfloat16* Qhi = g_Qhi + headoff;
    const __nv_bfloat16* Qlo = g_Qlo + headoff;
    const __nv_bfloat16* Khi = g_Khi + headoff;
    const __nv_bfloat16* Klo = g_Klo + headoff;
    const __nv_bfloat16* Vhi = g_Vhi + headoff;
    const __nv_bfloat16* Vlo = g_Vlo + headoff;
    const unsigned char* mb = mask + (size_t)b*SEQ;

    const uint32_t sb = smem_u32(sbuf);

    const int frow0 = tid >> 3;
    const int fcol  = tid & 7;
    const uint32_t swf0 = sw128((uint32_t)(frow0 * 128 + fcol * 16));
    const uint32_t swf1 = sw128((uint32_t)((frow0 + 32) * 128 + fcol * 16));

    #pragma unroll
    for (int i = 0; i < 4; i++) {
        const int f   = tid + i * 256;
        const int row = f >> 3;
        const int c   = f & 7;
        const size_t go = (size_t)(m0 + row) * DK + c * 8;
        const uint32_t sw = sw128((uint32_t)(row * 128 + c * 16));
        *(uint4*)(sbuf + sw)         = *(const uint4*)(Qhi + go);
        *(uint4*)(sbuf + 16384 + sw) = *(const uint4*)(Qlo + go);
    }
    __syncthreads();

    uint32_t qh[4][4], ql[4][4];
    #pragma unroll
    for (int ks = 0; ks < 4; ks++) {
        const uint32_t row = (uint32_t)(wid*16 + aRowHalf*8 + rr);
        const uint32_t off = sw128(row * 128 + (uint32_t)(ks*16 + aKHalf*8) * 2);
        ldmx4(qh[ks], sb + off);
        ldmx4(ql[ks], sb + 16384 + off);
    }
    __syncthreads();

    float oacc[8][4];
    #pragma unroll
    for (int nb = 0; nb < 8; nb++)
        #pragma unroll
        for (int i = 0; i < 4; i++) oacc[nb][i] = 0.f;
    float lrun0 = 0.f, lrun1 = 0.f;

    {
        const size_t g0 = (size_t)frow0 * DK + fcol * 8;
        const size_t g1 = (size_t)(frow0 + 32) * DK + fcol * 8;
        cp16(sb + swf0,         Khi + g0);  cp16(sb + swf1,         Khi + g1);
        cp16(sb +  8192 + swf0, Klo + g0);  cp16(sb +  8192 + swf1, Klo + g1);
        cp16(sb + 16384 + swf0, Vhi + g0);  cp16(sb + 16384 + swf1, Vhi + g1);
        cp16(sb + 24576 + swf0, Vlo + g0);  cp16(sb + 24576 + swf1, Vlo + g1);
        CP_COMMIT();
    }

    for (int t = 0; t < NT; t++) {
        const int kt = t * 64;
        const uint32_t cbuf = (uint32_t)(t & 1) * 32768;

        if (tid < 16) ((uint32_t*)smask)[tid] = *(const uint32_t*)(mb + kt + tid*4);

        if (t + 1 < NT) {
            const uint32_t nbuf = (uint32_t)((t + 1) & 1) * 32768;
            const size_t base = (size_t)(kt + 64) * DK;
            const size_t g0 = base + (size_t)frow0 * DK + fcol * 8;
            const size_t g1 = base + (size_t)(frow0 + 32) * DK + fcol * 8;
            cp16(sb + nbuf + swf0,         Khi + g0);  cp16(sb + nbuf + swf1,         Khi + g1);
            cp16(sb + nbuf +  8192 + swf0, Klo + g0);  cp16(sb + nbuf +  8192 + swf1, Klo + g1);
            cp16(sb + nbuf + 16384 + swf0, Vhi + g0);  cp16(sb + nbuf + 16384 + swf1, Vhi + g1);
            cp16(sb + nbuf + 24576 + swf0, Vlo + g0);  cp16(sb + nbuf + 24576 + swf1, Vlo + g1);
            CP_COMMIT();
            CP_WAIT(1);
        } else {
            CP_WAIT(0);
        }
        __syncthreads();

        // ---- QK^T: per ks, batch all B-fragments then 3 MMA passes (dist 8)
        float sacc[8][4];
        #pragma unroll
        for (int nt = 0; nt < 8; nt++)
            #pragma unroll
            for (int i = 0; i < 4; i++) sacc[nt][i] = 0.f;

        #pragma unroll
        for (int ks = 0; ks < 4; ks++) {
            uint32_t bh[4][4], bl[4][4];
            #pragma unroll
            for (int kg = 0; kg < 4; kg++) {
                const uint32_t row = (uint32_t)(kg*16 + bNb*8 + rr);
                const uint32_t off = sw128(row * 128 + (uint32_t)(ks*16 + bKHalf*8) * 2);
                ldmx4(bh[kg], sb + cbuf + off);
                ldmx4(bl[kg], sb + cbuf + 8192 + off);
            }
            #pragma unroll
            for (int kg = 0; kg < 4; kg++)
                #pragma unroll
                for (int sub = 0; sub < 2; sub++)
                    mma_bf16(sacc[kg*2+sub], qh[ks], bh[kg][sub*2], bh[kg][sub*2+1]);
            #pragma unroll
            for (int kg = 0; kg < 4; kg++)
                #pragma unroll
                for (int sub = 0; sub < 2; sub++)
                    mma_bf16(sacc[kg*2+sub], qh[ks], bl[kg][sub*2], bl[kg][sub*2+1]);
            #pragma unroll
            for (int kg = 0; kg < 4; kg++)
                #pragma unroll
                for (int sub = 0; sub < 2; sub++)
                    mma_bf16(sacc[kg*2+sub], ql[ks], bh[kg][sub*2], bh[kg][sub*2+1]);
        }

        // ---- clip (log2 domain), mask, p=exp2(s), pack PV fragments, sums
        uint32_t pah[4][4], pal[4][4];
        float rs0 = 0.f, rs1 = 0.f;
        #pragma unroll
        for (int nt = 0; nt < 8; nt++) {
            const int keyc = nt*8 + tg*2;
            const bool f0 = smask[keyc] != 0;
            const bool f1 = smask[keyc + 1] != 0;
            float s0 = fminf(fmaxf(sacc[nt][0], -CLIP_LOG2), CLIP_LOG2); if (f0) s0 = MASKED_S;
            float s1 = fminf(fmaxf(sacc[nt][1], -CLIP_LOG2), CLIP_LOG2); if (f1) s1 = MASKED_S;
            float s2 = fminf(fmaxf(sacc[nt][2], -CLIP_LOG2), CLIP_LOG2); if (f0) s2 = MASKED_S;
            float s3 = fminf(fmaxf(sacc[nt][3], -CLIP_LOG2), CLIP_LOG2); if (f1) s3 = MASKED_S;
            const float p0 = ex2(s0);
            const float p1 = ex2(s1);
            const float p2 = ex2(s2);
            const float p3 = ex2(s3);
            rs0 += p0 + p1;
            rs1 += p2 + p3;
            const int ks  = nt >> 1;
            const int sub = nt & 1;
            split_pack2(p0, p1, pah[ks][sub*2+0], pal[ks][sub*2+0]);
            split_pack2(p2, p3, pah[ks][sub*2+1], pal[ks][sub*2+1]);
        }
        rs0 += __shfl_xor_sync(0xffffffffu, rs0, 1);
        rs0 += __shfl_xor_sync(0xffffffffu, rs0, 2);
        rs1 += __shfl_xor_sync(0xffffffffu, rs1, 1);
        rs1 += __shfl_xor_sync(0xffffffffu, rs1, 2);
        lrun0 += rs0;
        lrun1 += rs1;

        // ---- PV: per ks, batch V-fragments then 3 MMA passes (dist 8)
        #pragma unroll
        for (int ks = 0; ks < 4; ks++) {
            uint32_t vh[4][4], vl[4][4];
            #pragma unroll
            for (int dg = 0; dg < 4; dg++) {
                const uint32_t key = (uint32_t)(ks*16 + vKey);
                const uint32_t off = sw128(key * 128 + (uint32_t)(dg*16 + vDh*8) * 2);
                ldmx4t(vh[dg], sb + cbuf + 16384 + off);
                ldmx4t(vl[dg], sb + cbuf + 24576 + off);
            }
            #pragma unroll
            for (int dg = 0; dg < 4; dg++)
                #pragma unroll
                for (int sub = 0; sub < 2; sub++)
                    mma_bf16(oacc[dg*2+sub], pah[ks], vh[dg][sub*2], vh[dg][sub*2+1]);
            #pragma unroll
            for (int dg = 0; dg < 4; dg++)
                #pragma unroll
                for (int sub = 0; sub < 2; sub++)
                    mma_bf16(oacc[dg*2+sub], pah[ks], vl[dg][sub*2], vl[dg][sub*2+1]);
            #pragma unroll
            for (int dg = 0; dg < 4; dg++)
                #pragma unroll
                for (int sub = 0; sub < 2; sub++)
                    mma_bf16(oacc[dg*2+sub], pal[ks], vh[dg][sub*2], vh[dg][sub*2+1]);
        }
        __syncthreads();
    }

    const float inv0 = 1.f / lrun0;
    const float inv1 = 1.f / lrun1;
    const int row0 = m0 + wid*16 + gID;
    const int row1 = row0 + 8;
    const size_t o0 = ((size_t)(b*SEQ + row0))*D_MODEL + h*DK;
    const size_t o1 = ((size_t)(b*SEQ + row1))*D_MODEL + h*DK;
    #pragma unroll
    for (int nb = 0; nb < 8; nb++) {
        const int col = nb*8 + tg*2;
        uint32_t H, L;
        split_pack2(oacc[nb][0]*inv0, oacc[nb][1]*inv0, H, L);
        *(uint32_t*)(g_ctxhi + o0 + col) = H;
        *(uint32_t*)(g_ctxlo + o0 + col) = L;
        split_pack2(oacc[nb][2]*inv1, oacc[nb][3]*inv1, H, L);
        *(uint32_t*)(g_ctxhi + o1 + col) = H;
        *(uint32_t*)(g_ctxlo + o1 + col) = L;
    }
}

// ---------------------------------------------------------------------------
extern "C" void kernel_launch(void* const* d_in, const int* in_sizes, int n_in,
                              void* d_out, int out_size)
{
    const float* x  = (const float*)d_in[0];
    const unsigned char* mask = (const unsigned char*)d_in[1];
    const float* Wq = (const float*)d_in[2];
    const float* bq = (const float*)d_in[3];
    const float* Wk = (const float*)d_in[4];
    const float* bk = (const float*)d_in[5];
    const float* Wv = (const float*)d_in[6];
    const float* bv = (const float*)d_in[7];
    const float* Wo = (const float*)d_in[8];
    const float* bo = (const float*)d_in[9];
    float* out = (float*)d_out;

    cudaFuncSetAttribute(attn_hmma_kernel,
                         cudaFuncAttributeMaxDynamicSharedMemorySize, ATTN_SMEM);
    cudaFuncSetAttribute(hmma_gemm_kernel<true>,
                         cudaFuncAttributeMaxDynamicSharedMemorySize, GEMM_SMEM);
    cudaFuncSetAttribute(hmma_gemm_kernel<false>,
                         cudaFuncAttributeMaxDynamicSharedMemorySize, GEMM_SMEM);

    split_x_kernel<<<M_ROWS*D_MODEL/4/256, 256>>>(x);
    split_w_kernel<<<dim3(D_MODEL*D_MODEL/4/256, 4), 256>>>(Wq, Wk, Wv, Wo);

    hmma_gemm_kernel<true><<<dim3(48, M_ROWS/128), 256, GEMM_SMEM>>>(bq, bk, bv, nullptr);

    attn_hmma_kernel<<<dim3(SEQ/128, NHEAD, BATCH), 256, ATTN_SMEM>>>(mask);

    hmma_gemm_kernel<false><<<dim3(16, M_ROWS/128), 256, GEMM_SMEM>>>(bo, bo, bo, out);
}

// round 11
// speedup vs baseline: 1.3477x; 1.0290x over previous
#include <cuda_runtime.h>
#include <cuda_bf16.h>
#include <math.h>
#include <stdint.h>

#define D_MODEL 1024
#define NHEAD   16
#define DK      64
#define BATCH   4
#define SEQ     2048
#define M_ROWS  (BATCH*SEQ)   // 8192
#define HQKV    (BATCH*NHEAD*SEQ*DK)

// log2(e) folded constants
#define Q_PRESCALE 0.18033688011112042f   // 0.125 * log2(e)
#define CLIP_LOG2  72.13475204444817f     // 50 * log2(e)
#define MASKED_S   (-14427.0f)            // exp2 -> 0

// Inter-kernel interchange: bf16 hi/lo pairs (value = hi+lo, err ~2^-18 rel)
__device__ __align__(16) __nv_bfloat16 g_xhi[M_ROWS*D_MODEL];
__device__ __align__(16) __nv_bfloat16 g_xlo[M_ROWS*D_MODEL];
__device__ __align__(16) __nv_bfloat16 g_Whi[4*D_MODEL*D_MODEL];   // q,k,v,o
__device__ __align__(16) __nv_bfloat16 g_Wlo[4*D_MODEL*D_MODEL];
__device__ __align__(16) __nv_bfloat16 g_Qhi[HQKV];  // pre-scaled by 0.125*log2e
__device__ __align__(16) __nv_bfloat16 g_Qlo[HQKV];
__device__ __align__(16) __nv_bfloat16 g_Khi[HQKV];
__device__ __align__(16) __nv_bfloat16 g_Klo[HQKV];
__device__ __align__(16) __nv_bfloat16 g_Vhi[HQKV];
__device__ __align__(16) __nv_bfloat16 g_Vlo[HQKV];
__device__ __align__(16) __nv_bfloat16 g_ctxhi[M_ROWS*D_MODEL];
__device__ __align__(16) __nv_bfloat16 g_ctxlo[M_ROWS*D_MODEL];

// ---------------------------------------------------------------------------
__device__ __forceinline__ void ldmx4(uint32_t* r, uint32_t addr) {
    asm volatile("ldmatrix.sync.aligned.m8n8.x4.shared.b16 {%0,%1,%2,%3}, [%4];"
                 : "=r"(r[0]), "=r"(r[1]), "=r"(r[2]), "=r"(r[3]) : "r"(addr));
}
__device__ __forceinline__ void ldmx4t(uint32_t* r, uint32_t addr) {
    asm volatile("ldmatrix.sync.aligned.m8n8.x4.trans.shared.b16 {%0,%1,%2,%3}, [%4];"
                 : "=r"(r[0]), "=r"(r[1]), "=r"(r[2]), "=r"(r[3]) : "r"(addr));
}
__device__ __forceinline__ void mma_bf16(float* d, const uint32_t* a,
                                         uint32_t b0, uint32_t b1) {
    asm volatile(
        "mma.sync.aligned.m16n8k16.row.col.f32.bf16.bf16.f32 "
        "{%0,%1,%2,%3}, {%4,%5,%6,%7}, {%8,%9}, {%0,%1,%2,%3};"
        : "+f"(d[0]), "+f"(d[1]), "+f"(d[2]), "+f"(d[3])
        : "r"(a[0]), "r"(a[1]), "r"(a[2]), "r"(a[3]), "r"(b0), "r"(b1));
}
__device__ __forceinline__ uint32_t smem_u32(const void* p) {
    uint32_t a;
    asm("{ .reg .u64 t; cvta.to.shared.u64 t, %1; cvt.u32.u64 %0, t; }"
        : "=r"(a) : "l"(p));
    return a;
}
__device__ __forceinline__ void cp16(uint32_t saddr, const void* g) {
    asm volatile("cp.async.cg.shared.global [%0], [%1], 16;"
                 :: "r"(saddr), "l"(g) : "memory");
}
#define CP_COMMIT()   asm volatile("cp.async.commit_group;" ::: "memory")
#define CP_WAIT(n)    asm volatile("cp.async.wait_group %0;" :: "n"(n) : "memory")

__device__ __forceinline__ uint32_t sw128(uint32_t off) {
    return off ^ ((off >> 3) & 0x70);
}
__device__ __forceinline__ float ex2(float x) {
    float y;
    asm("ex2.approx.f32 %0, %1;" : "=f"(y) : "f"(x));
    return y;
}
__device__ __forceinline__ void split4(float4 v, uint2& H, uint2& L) {
    __nv_bfloat162 h0 = __floats2bfloat162_rn(v.x, v.y);
    __nv_bfloat162 h1 = __floats2bfloat162_rn(v.z, v.w);
    H.x = *reinterpret_cast<uint32_t*>(&h0);
    H.y = *reinterpret_cast<uint32_t*>(&h1);
    float rx = v.x - __uint_as_float(H.x << 16);
    float ry = v.y - __uint_as_float(H.x & 0xFFFF0000u);
    float rz = v.z - __uint_as_float(H.y << 16);
    float rw = v.w - __uint_as_float(H.y & 0xFFFF0000u);
    __nv_bfloat162 l0 = __floats2bfloat162_rn(rx, ry);
    __nv_bfloat162 l1 = __floats2bfloat162_rn(rz, rw);
    L.x = *reinterpret_cast<uint32_t*>(&l0);
    L.y = *reinterpret_cast<uint32_t*>(&l1);
}
__device__ __forceinline__ void split_pack2(float a, float b, uint32_t& H, uint32_t& L) {
    __nv_bfloat162 h2 = __floats2bfloat162_rn(a, b);
    H = *reinterpret_cast<uint32_t*>(&h2);
    float fa = __uint_as_float(H << 16);
    float fb = __uint_as_float(H & 0xFFFF0000u);
    __nv_bfloat162 l2 = __floats2bfloat162_rn(a - fa, b - fb);
    L = *reinterpret_cast<uint32_t*>(&l2);
}

// ---------------------------------------------------------------------------
// Pre-split kernels (memory-bound, one-shot)
// ---------------------------------------------------------------------------
__global__ __launch_bounds__(256) void split_x_kernel(const float* __restrict__ x) {
    const int i = blockIdx.x * 256 + threadIdx.x;
    float4 v = ((const float4*)x)[i];
    v.x += 1e-8f; v.y += 1e-8f; v.z += 1e-8f; v.w += 1e-8f;
    uint2 H, L;
    split4(v, H, L);
    ((uint2*)g_xhi)[i] = H;
    ((uint2*)g_xlo)[i] = L;
}

__global__ __launch_bounds__(256) void split_w_kernel(const float* __restrict__ W0,
                                                      const float* __restrict__ W1,
                                                      const float* __restrict__ W2,
                                                      const float* __restrict__ W3) {
    const int which = blockIdx.y;
    const float* W = which == 0 ? W0 : which == 1 ? W1 : which == 2 ? W2 : W3;
    const int i = blockIdx.x * 256 + threadIdx.x;
    float4 v = ((const float4*)W)[i];
    uint2 H, L;
    split4(v, H, L);
    const size_t o = (size_t)which * (D_MODEL*D_MODEL/4) + i;
    ((uint2*)g_Whi)[o] = H;
    ((uint2*)g_Wlo)[o] = L;
}

// ---------------------------------------------------------------------------
// HMMA GEMM v3 (unchanged from R10): cp.async double-buffered + 3-pass MMA.
// ---------------------------------------------------------------------------
#define GEMM_BUF   49152
#define GEMM_SMEM  (2*GEMM_BUF)

template<bool QKV>
__global__ __launch_bounds__(256)
void hmma_gemm_kernel(const float* __restrict__ b0v,
                      const float* __restrict__ b1v,
                      const float* __restrict__ b2v,
                      float* __restrict__ outp)
{
    extern __shared__ __align__(1024) unsigned char gsm[];

    const int tid  = threadIdx.x;
    const int wid  = tid >> 5;
    const int lane = tid & 31;
    const int mw   = wid & 3;
    const int nw   = wid >> 2;

    const int bx    = blockIdx.x;
    const int which = QKV ? (bx >> 4) : 3;
    const int n0    = (bx & 15) * 64;
    const int m0    = blockIdx.y * 128;

    const __nv_bfloat16* Ahi = QKV ? g_xhi : g_ctxhi;
    const __nv_bfloat16* Alo = QKV ? g_xlo : g_ctxlo;
    const __nv_bfloat16* Whi = g_Whi + (size_t)which * D_MODEL * D_MODEL;
    const __nv_bfloat16* Wlo = g_Wlo + (size_t)which * D_MODEL * D_MODEL;
    const float* bias = QKV ? (which == 0 ? b0v : which == 1 ? b1v : b2v) : b0v;

    const uint32_t sb = smem_u32(gsm);

    const int blk      = lane >> 3;
    const int rr       = lane & 7;
    const int aRowHalf = blk & 1;
    const int aKHalf   = blk >> 1;
    const int bNb      = blk >> 1;
    const int bKHalf   = blk & 1;

    const int frow = tid >> 3;
    const int fcol = tid & 7;
    uint32_t swA[4], swB[2];
    #pragma unroll
    for (int i = 0; i < 4; i++)
        swA[i] = sw128((uint32_t)((frow + i*32) * 128 + fcol * 16));
    swB[0] = swA[0];
    swB[1] = swA[1];

    float acc[2][4][4];
    #pragma unroll
    for (int i=0;i<2;i++)
        #pragma unroll
        for (int j=0;j<4;j++)
            #pragma unroll
            for (int l=0;l<4;l++) acc[i][j][l]=0.f;

    {
        #pragma unroll
        for (int i = 0; i < 4; i++) {
            const size_t go = (size_t)(m0 + frow + i*32) * D_MODEL + fcol * 8;
            cp16(sb + swA[i],         Ahi + go);
            cp16(sb + 16384 + swA[i], Alo + go);
        }
        #pragma unroll
        for (int i = 0; i < 2; i++) {
            const size_t go = (size_t)(n0 + frow + i*32) * D_MODEL + fcol * 8;
            cp16(sb + 32768 + swB[i], Whi + go);
            cp16(sb + 40960 + swB[i], Wlo + go);
        }
        CP_COMMIT();
    }

    for (int chunk = 0; chunk < 16; chunk++) {
        const uint32_t cbuf = (uint32_t)(chunk & 1) * GEMM_BUF;

        if (chunk + 1 < 16) {
            const uint32_t nbuf = (uint32_t)((chunk + 1) & 1) * GEMM_BUF;
            const int k1 = (chunk + 1) * 64;
            #pragma unroll
            for (int i = 0; i < 4; i++) {
                const size_t go = (size_t)(m0 + frow + i*32) * D_MODEL + k1 + fcol * 8;
                cp16(sb + nbuf + swA[i],         Ahi + go);
                cp16(sb + nbuf + 16384 + swA[i], Alo + go);
            }
            #pragma unroll
            for (int i = 0; i < 2; i++) {
                const size_t go = (size_t)(n0 + frow + i*32) * D_MODEL + k1 + fcol * 8;
                cp16(sb + nbuf + 32768 + swB[i], Whi + go);
                cp16(sb + nbuf + 40960 + swB[i], Wlo + go);
            }
            CP_COMMIT();
            CP_WAIT(1);
        } else {
            CP_WAIT(0);
        }
        __syncthreads();

        #pragma unroll
        for (int ks = 0; ks < 4; ks++) {
            uint32_t ah[2][4], al[2][4];
            #pragma unroll
            for (int mf = 0; mf < 2; mf++) {
                const uint32_t row = (uint32_t)(mw*32 + mf*16 + aRowHalf*8 + rr);
                const uint32_t off = sw128(row * 128 + (uint32_t)(ks*16 + aKHalf*8) * 2);
                ldmx4(ah[mf], sb + cbuf + off);
                ldmx4(al[mf], sb + cbuf + 16384 + off);
            }
            uint32_t bh[2][4], bl[2][4];
            #pragma unroll
            for (int pr = 0; pr < 2; pr++) {
                const uint32_t n   = (uint32_t)(nw*32 + pr*16 + bNb*8 + rr);
                const uint32_t off = sw128(n * 128 + (uint32_t)(ks*16 + bKHalf*8) * 2);
                ldmx4(bh[pr], sb + cbuf + 32768 + off);
                ldmx4(bl[pr], sb + cbuf + 40960 + off);
            }
            #pragma unroll
            for (int mf = 0; mf < 2; mf++)
                #pragma unroll
                for (int nb = 0; nb < 4; nb++)
                    mma_bf16(acc[mf][nb], ah[mf], bh[nb>>1][(nb&1)*2], bh[nb>>1][(nb&1)*2+1]);
            #pragma unroll
            for (int mf = 0; mf < 2; mf++)
                #pragma unroll
                for (int nb = 0; nb < 4; nb++)
                    mma_bf16(acc[mf][nb], ah[mf], bl[nb>>1][(nb&1)*2], bl[nb>>1][(nb&1)*2+1]);
            #pragma unroll
            for (int mf = 0; mf < 2; mf++)
                #pragma unroll
                for (int nb = 0; nb < 4; nb++)
                    mma_bf16(acc[mf][nb], al[mf], bh[nb>>1][(nb&1)*2], bh[nb>>1][(nb&1)*2+1]);
        }
        __syncthreads();
    }

    const int gID = lane >> 2;
    const int tg  = lane & 3;

    #pragma unroll
    for (int mf = 0; mf < 2; mf++) {
        #pragma unroll
        for (int nb = 0; nb < 4; nb++) {
            const int colL = nw*32 + nb*8 + tg*2;
            const float bb0 = bias[n0 + colL];
            const float bb1 = bias[n0 + colL + 1];
            #pragma unroll
            for (int half = 0; half < 2; half++) {
                const int m = m0 + mw*32 + mf*16 + half*8 + gID;
                if (QKV && which < 3) {
                    float v0 = fminf(fmaxf(acc[mf][nb][half*2+0] + bb0, -10.f), 10.f);
                    float v1 = fminf(fmaxf(acc[mf][nb][half*2+1] + bb1, -10.f), 10.f);
                    if (which == 0) { v0 *= Q_PRESCALE; v1 *= Q_PRESCALE; }
                    uint32_t H, L;
                    split_pack2(v0, v1, H, L);
                    const int b_ = m >> 11;
                    const int t  = m & (SEQ - 1);
                    const int h  = bx & 15;
                    const size_t o = (((size_t)(b_*NHEAD + h))*SEQ + t)*DK + colL;
                    __nv_bfloat16* dh = (which == 0) ? g_Qhi : (which == 1) ? g_Khi : g_Vhi;
                    __nv_bfloat16* dl = (which == 0) ? g_Qlo : (which == 1) ? g_Klo : g_Vlo;
                    *(uint32_t*)(dh + o) = H;
                    *(uint32_t*)(dl + o) = L;
                } else {
                    float2 v;
                    v.x = fminf(fmaxf(acc[mf][nb][half*2+0] + bb0, -100.f), 100.f);
                    v.y = fminf(fmaxf(acc[mf][nb][half*2+1] + bb1, -100.f), 100.f);
                    *(float2*)(outp + (size_t)m * D_MODEL + n0 + colL) = v;
                }
            }
        }
    }
}

// ---------------------------------------------------------------------------
// HMMA flash attention v5: 128-thread CTAs (4 warps, 64 q-rows) so 2 CTAs
// co-reside per SM — one CTA's softmax scalar phase overlaps the other's
// MMAs. K/V tile smem unchanged (2 x 32KB double buffer); per-warp compute
// identical to v4 (16 q-rows/warp, 3-pass MMA, exp2 softmax).
// ---------------------------------------------------------------------------
#define ATTN_SMEM 65536
#define NT (SEQ/64)

__global__ __launch_bounds__(128, 2)
void attn_hmma_kernel(const unsigned char* __restrict__ mask)
{
    extern __shared__ __align__(1024) unsigned char sbuf[];
    __shared__ unsigned char smask[64];

    const int tid  = threadIdx.x;
    const int wid  = tid >> 5;          // 0..3
    const int lane = tid & 31;
    const int gID  = lane >> 2;
    const int tg   = lane & 3;

    const int blk      = lane >> 3;
    const int rr       = lane & 7;
    const int aRowHalf = blk & 1;
    const int aKHalf   = blk >> 1;
    const int bNb      = blk >> 1;
    const int bKHalf   = blk & 1;

    const int vKey = lane & 15;
    const int vDh  = lane >> 4;

    const int qt = blockIdx.x;          // 0..31
    const int h  = blockIdx.y;
    const int b  = blockIdx.z;
    const int m0 = qt * 64;

    const size_t headoff = ((size_t)(b*NHEAD + h))*SEQ*DK;
    const __nv_bfloat16* Qhi = g_Qhi + headoff;
    const __nv_bfloat16* Qlo = g_Qlo + headoff;
    const __nv_bfloat16* Khi = g_Khi + headoff;
    const __nv_bfloat16* Klo = g_Klo + headoff;
    const __nv_bfloat16* Vhi = g_Vhi + headoff;
    const __nv_bfloat16* Vlo = g_Vlo + headoff;
    const unsigned char* mb = mask + (size_t)b*SEQ;

    const uint32_t sb = smem_u32(sbuf);

    // K/V fill addressing: 64 rows x 8 cols of 16B per component; 128 threads
    // -> 4 row-groups of 16 per thread.
    const int frow = tid >> 3;          // 0..15
    const int fcol = tid & 7;           // 0..7
    uint32_t swf[4];
    #pragma unroll
    for (int i = 0; i < 4; i++)
        swf[i] = sw128((uint32_t)((frow + i*16) * 128 + fcol * 16));

    // ---- Phase 0: Q tile 64x64 bf16 (pre-scaled) -> smem -> registers
    // Qhi at 0 (8KB), Qlo at 8192.
    #pragma unroll
    for (int i = 0; i < 4; i++) {
        const int f   = tid + i * 128;      // 0..511
        const int row = f >> 3;             // 0..63
        const int c   = f & 7;
        const size_t go = (size_t)(m0 + row) * DK + c * 8;
        const uint32_t sw = sw128((uint32_t)(row * 128 + c * 16));
        *(uint4*)(sbuf + sw)        = *(const uint4*)(Qhi + go);
        *(uint4*)(sbuf + 8192 + sw) = *(const uint4*)(Qlo + go);
    }
    __syncthreads();

    uint32_t qh[4][4], ql[4][4];
    #pragma unroll
    for (int ks = 0; ks < 4; ks++) {
        const uint32_t row = (uint32_t)(wid*16 + aRowHalf*8 + rr);
        const uint32_t off = sw128(row * 128 + (uint32_t)(ks*16 + aKHalf*8) * 2);
        ldmx4(qh[ks], sb + off);
        ldmx4(ql[ks], sb + 8192 + off);
    }
    __syncthreads();   // Q smem dead; overlay with K/V buffers

    float oacc[8][4];
    #pragma unroll
    for (int nb = 0; nb < 8; nb++)
        #pragma unroll
        for (int i = 0; i < 4; i++) oacc[nb][i] = 0.f;
    float lrun0 = 0.f, lrun1 = 0.f;

    // ---- prologue: async-load tile 0 into buffer 0
    {
        #pragma unroll
        for (int i = 0; i < 4; i++) {
            const size_t g = (size_t)(frow + i*16) * DK + fcol * 8;
            cp16(sb + swf[i],         Khi + g);
            cp16(sb +  8192 + swf[i], Klo + g);
            cp16(sb + 16384 + swf[i], Vhi + g);
            cp16(sb + 24576 + swf[i], Vlo + g);
        }
        CP_COMMIT();
    }

    for (int t = 0; t < NT; t++) {
        const int kt = t * 64;
        const uint32_t cbuf = (uint32_t)(t & 1) * 32768;

        if (tid < 16) ((uint32_t*)smask)[tid] = *(const uint32_t*)(mb + kt + tid*4);

        if (t + 1 < NT) {
            const uint32_t nbuf = (uint32_t)((t + 1) & 1) * 32768;
            const size_t base = (size_t)(kt + 64) * DK;
            #pragma unroll
            for (int i = 0; i < 4; i++) {
                const size_t g = base + (size_t)(frow + i*16) * DK + fcol * 8;
                cp16(sb + nbuf + swf[i],         Khi + g);
                cp16(sb + nbuf +  8192 + swf[i], Klo + g);
                cp16(sb + nbuf + 16384 + swf[i], Vhi + g);
                cp16(sb + nbuf + 24576 + swf[i], Vlo + g);
            }
            CP_COMMIT();
            CP_WAIT(1);
        } else {
            CP_WAIT(0);
        }
        __syncthreads();

        // ---- QK^T: per ks, batch B-fragments then 3 MMA passes (dist 8)
        float sacc[8][4];
        #pragma unroll
        for (int nt = 0; nt < 8; nt++)
            #pragma unroll
            for (int i = 0; i < 4; i++) sacc[nt][i] = 0.f;

        #pragma unroll
        for (int ks = 0; ks < 4; ks++) {
            uint32_t bh[4][4], bl[4][4];
            #pragma unroll
            for (int kg = 0; kg < 4; kg++) {
                const uint32_t row = (uint32_t)(kg*16 + bNb*8 + rr);
                const uint32_t off = sw128(row * 128 + (uint32_t)(ks*16 + bKHalf*8) * 2);
                ldmx4(bh[kg], sb + cbuf + off);
                ldmx4(bl[kg], sb + cbuf + 8192 + off);
            }
            #pragma unroll
            for (int kg = 0; kg < 4; kg++)
                #pragma unroll
                for (int sub = 0; sub < 2; sub++)
                    mma_bf16(sacc[kg*2+sub], qh[ks], bh[kg][sub*2], bh[kg][sub*2+1]);
            #pragma unroll
            for (int kg = 0; kg < 4; kg++)
                #pragma unroll
                for (int sub = 0; sub < 2; sub++)
                    mma_bf16(sacc[kg*2+sub], qh[ks], bl[kg][sub*2], bl[kg][sub*2+1]);
            #pragma unroll
            for (int kg = 0; kg < 4; kg++)
                #pragma unroll
                for (int sub = 0; sub < 2; sub++)
                    mma_bf16(sacc[kg*2+sub], ql[ks], bh[kg][sub*2], bh[kg][sub*2+1]);
        }

        // ---- clip (log2 domain), mask, p=exp2(s), pack PV fragments, sums
        uint32_t pah[4][4], pal[4][4];
        float rs0 = 0.f, rs1 = 0.f;
        #pragma unroll
        for (int nt = 0; nt < 8; nt++) {
            const int keyc = nt*8 + tg*2;
            const bool f0 = smask[keyc] != 0;
            const bool f1 = smask[keyc + 1] != 0;
            float s0 = fminf(fmaxf(sacc[nt][0], -CLIP_LOG2), CLIP_LOG2); if (f0) s0 = MASKED_S;
            float s1 = fminf(fmaxf(sacc[nt][1], -CLIP_LOG2), CLIP_LOG2); if (f1) s1 = MASKED_S;
            float s2 = fminf(fmaxf(sacc[nt][2], -CLIP_LOG2), CLIP_LOG2); if (f0) s2 = MASKED_S;
            float s3 = fminf(fmaxf(sacc[nt][3], -CLIP_LOG2), CLIP_LOG2); if (f1) s3 = MASKED_S;
            const float p0 = ex2(s0);
            const float p1 = ex2(s1);
            const float p2 = ex2(s2);
            const float p3 = ex2(s3);
            rs0 += p0 + p1;
            rs1 += p2 + p3;
            const int ks  = nt >> 1;
            const int sub = nt & 1;
            split_pack2(p0, p1, pah[ks][sub*2+0], pal[ks][sub*2+0]);
            split_pack2(p2, p3, pah[ks][sub*2+1], pal[ks][sub*2+1]);
        }
        rs0 += __shfl_xor_sync(0xffffffffu, rs0, 1);
        rs0 += __shfl_xor_sync(0xffffffffu, rs0, 2);
        rs1 += __shfl_xor_sync(0xffffffffu, rs1, 1);
        rs1 += __shfl_xor_sync(0xffffffffu, rs1, 2);
        lrun0 += rs0;
        lrun1 += rs1;

        // ---- PV: per ks, batch V-fragments then 3 MMA passes (dist 8)
        #pragma unroll
        for (int ks = 0; ks < 4; ks++) {
            uint32_t vh[4][4], vl[4][4];
            #pragma unroll
            for (int dg = 0; dg < 4; dg++) {
                const uint32_t key = (uint32_t)(ks*16 + vKey);
                const uint32_t off = sw128(key * 128 + (uint32_t)(dg*16 + vDh*8) * 2);
                ldmx4t(vh[dg], sb + cbuf + 16384 + off);
                ldmx4t(vl[dg], sb + cbuf + 24576 + off);
            }
            #pragma unroll
            for (int dg = 0; dg < 4; dg++)
                #pragma unroll
                for (int sub = 0; sub < 2; sub++)
                    mma_bf16(oacc[dg*2+sub], pah[ks], vh[dg][sub*2], vh[dg][sub*2+1]);
            #pragma unroll
            for (int dg = 0; dg < 4; dg++)
                #pragma unroll
                for (int sub = 0; sub < 2; sub++)
                    mma_bf16(oacc[dg*2+sub], pah[ks], vl[dg][sub*2], vl[dg][sub*2+1]);
            #pragma unroll
            for (int dg = 0; dg < 4; dg++)
                #pragma unroll
                for (int sub = 0; sub < 2; sub++)
                    mma_bf16(oacc[dg*2+sub], pal[ks], vh[dg][sub*2], vh[dg][sub*2+1]);
        }
        __syncthreads();
    }

    const float inv0 = 1.f / lrun0;
    const float inv1 = 1.f / lrun1;
    const int row0 = m0 + wid*16 + gID;
    const int row1 = row0 + 8;
    const size_t o0 = ((size_t)(b*SEQ + row0))*D_MODEL + h*DK;
    const size_t o1 = ((size_t)(b*SEQ + row1))*D_MODEL + h*DK;
    #pragma unroll
    for (int nb = 0; nb < 8; nb++) {
        const int col = nb*8 + tg*2;
        uint32_t H, L;
        split_pack2(oacc[nb][0]*inv0, oacc[nb][1]*inv0, H, L);
        *(uint32_t*)(g_ctxhi + o0 + col) = H;
        *(uint32_t*)(g_ctxlo + o0 + col) = L;
        split_pack2(oacc[nb][2]*inv1, oacc[nb][3]*inv1, H, L);
        *(uint32_t*)(g_ctxhi + o1 + col) = H;
        *(uint32_t*)(g_ctxlo + o1 + col) = L;
    }
}

// ---------------------------------------------------------------------------
extern "C" void kernel_launch(void* const* d_in, const int* in_sizes, int n_in,
                              void* d_out, int out_size)
{
    const float* x  = (const float*)d_in[0];
    const unsigned char* mask = (const unsigned char*)d_in[1];
    const float* Wq = (const float*)d_in[2];
    const float* bq = (const float*)d_in[3];
    const float* Wk = (const float*)d_in[4];
    const float* bk = (const float*)d_in[5];
    const float* Wv = (const float*)d_in[6];
    const float* bv = (const float*)d_in[7];
    const float* Wo = (const float*)d_in[8];
    const float* bo = (const float*)d_in[9];
    float* out = (float*)d_out;

    cudaFuncSetAttribute(attn_hmma_kernel,
                         cudaFuncAttributeMaxDynamicSharedMemorySize, ATTN_SMEM);
    cudaFuncSetAttribute(hmma_gemm_kernel<true>,
                         cudaFuncAttributeMaxDynamicSharedMemorySize, GEMM_SMEM);
    cudaFuncSetAttribute(hmma_gemm_kernel<false>,
                         cudaFuncAttributeMaxDynamicSharedMemorySize, GEMM_SMEM);

    split_x_kernel<<<M_ROWS*D_MODEL/4/256, 256>>>(x);
    split_w_kernel<<<dim3(D_MODEL*D_MODEL/4/256, 4), 256>>>(Wq, Wk, Wv, Wo);

    hmma_gemm_kernel<true><<<dim3(48, M_ROWS/128), 256, GEMM_SMEM>>>(bq, bk, bv, nullptr);

    attn_hmma_kernel<<<dim3(SEQ/64, NHEAD, BATCH), 128, ATTN_SMEM>>>(mask);

    hmma_gemm_kernel<false><<<dim3(16, M_ROWS/128), 256, GEMM_SMEM>>>(bo, bo, bo, out);
}